// round 1
// baseline (speedup 1.0000x reference)
#include <cuda_runtime.h>
#include <math.h>

// ---------------------------------------------------------------------------
// AnnoCluster: encoder MLP -> t-dist cluster assign -> two decoder MLPs.
// Round 1: fp32 SIMT SGEMM baseline (correctness + FFMA-bound timing anchor).
// ---------------------------------------------------------------------------

#define SPLITS 8
#define MAXB 4096
#define MAXH 128

// Scratch (device globals -- no allocation allowed in kernel_launch)
__device__ float g_part[SPLITS * MAXB * MAXH];   // split-K partials for GEMM1
__device__ float g_h1[MAXB * MAXH];              // encoder hidden (post-ReLU)
__device__ float g_hd[2 * MAXB * MAXH];          // decoder hiddens [e, q]

// ---------------------------------------------------------------------------
// Generic tiled SGEMM: C[M,N] = A[M,*](lda) @ W[*,N](ldw) over K range.
// blockIdx.z selects a K-chunk (split-K); partStride offsets C per chunk.
// EPI_BIAS: add bias[n] on store (used for the final decoder GEMMs).
// ---------------------------------------------------------------------------
template <int BM, int BN, int BK, int TM, int TN, bool EPI_BIAS>
__global__ __launch_bounds__((BM / TM) * (BN / TN))
void sgemm_kernel(const float* __restrict__ A, const float* __restrict__ W,
                  const float* __restrict__ bias, float* __restrict__ C,
                  int M, int N, int lda, int ldw, int ldc,
                  int Kd, int chunkK, long long partStride)
{
    __shared__ float As[BK][BM];
    __shared__ float Ws[BK][BN];
    constexpr int THREADS = (BM / TM) * (BN / TN);

    const int tid = threadIdx.x;
    const int tx = tid % (BN / TN);
    const int ty = tid / (BN / TN);
    const int mBase = blockIdx.y * BM;
    const int nBase = blockIdx.x * BN;

    const int kStart = blockIdx.z * chunkK;
    const int kEnd = min(Kd, kStart + chunkK);
    C += (long long)blockIdx.z * partStride;

    float acc[TM][TN];
#pragma unroll
    for (int i = 0; i < TM; i++)
#pragma unroll
        for (int j = 0; j < TN; j++) acc[i][j] = 0.f;

    for (int k0 = kStart; k0 < kEnd; k0 += BK) {
        // Load A tile (transposed into smem: As[k][m])
#pragma unroll
        for (int e = tid; e < BM * BK; e += THREADS) {
            int am = e / BK, ak = e % BK;
            int gm = mBase + am, gk = k0 + ak;
            float v = 0.f;
            if (gm < M && gk < kEnd) v = A[(long long)gm * lda + gk];
            As[ak][am] = v;
        }
        // Load W tile (Ws[k][n]) -- coalesced along n
#pragma unroll
        for (int e = tid; e < BK * BN; e += THREADS) {
            int wk = e / BN, wn = e % BN;
            int gk = k0 + wk, gn = nBase + wn;
            float v = 0.f;
            if (gk < kEnd && gn < N) v = W[(long long)gk * ldw + gn];
            Ws[wk][wn] = v;
        }
        __syncthreads();

#pragma unroll
        for (int kk = 0; kk < BK; kk++) {
            float a[TM], b[TN];
#pragma unroll
            for (int i = 0; i < TM; i++) a[i] = As[kk][ty * TM + i];
#pragma unroll
            for (int j = 0; j < TN; j++) b[j] = Ws[kk][tx * TN + j];
#pragma unroll
            for (int i = 0; i < TM; i++)
#pragma unroll
                for (int j = 0; j < TN; j++)
                    acc[i][j] = fmaf(a[i], b[j], acc[i][j]);
        }
        __syncthreads();
    }

#pragma unroll
    for (int i = 0; i < TM; i++) {
        int gm = mBase + ty * TM + i;
        if (gm >= M) continue;
#pragma unroll
        for (int j = 0; j < TN; j++) {
            int gn = nBase + tx * TN + j;
            if (gn >= N) continue;
            float v = acc[i][j];
            if (EPI_BIAS) v += bias[gn];
            C[(long long)gm * ldc + gn] = v;
        }
    }
}

// Reduce split-K partials, add bias, ReLU -> g_h1
__global__ void h1_epilogue_kernel(const float* __restrict__ bias, int MH, int H)
{
    int i = blockIdx.x * blockDim.x + threadIdx.x;
    if (i >= MH) return;
    float s = 0.f;
#pragma unroll
    for (int p = 0; p < SPLITS; p++) s += g_part[(long long)p * MH + i];
    s += bias[i % H];
    g_h1[i] = fmaxf(s, 0.f);
}

// z_e = g_h1 @ enc_w2 + b2    (one thread per (b,z); warp spans one row's Z)
__global__ void zenc_kernel(const float* __restrict__ w2, const float* __restrict__ b2,
                            float* __restrict__ ze, int B, int H, int Z)
{
    int t = blockIdx.x * blockDim.x + threadIdx.x;
    if (t >= B * Z) return;
    int b = t / Z, z = t % Z;
    const float* h1 = g_h1 + (long long)b * H;
    float acc = b2[z];
    for (int k = 0; k < H; k++) acc = fmaf(h1[k], w2[k * Z + z], acc);
    ze[t] = acc;
}

// Per-row: distances to centroids, t-kernel, normalize, argmax, gather z_q.
#define MAXZ 64
#define MAXK 64
__global__ void cluster_kernel(const float* __restrict__ ze, const float* __restrict__ emb,
                               float* __restrict__ zq, float* __restrict__ kout,
                               float* __restrict__ zd, float* __restrict__ dp,
                               int B, int Z, int K)
{
    int b = blockIdx.x * blockDim.x + threadIdx.x;
    if (b >= B) return;

    float zrow[MAXZ];
    for (int z = 0; z < Z; z++) zrow[z] = ze[(long long)b * Z + z];

    float p[MAXK];
    float sum = 0.f;
    for (int k = 0; k < K; k++) {
        float d = 0.f;
        for (int z = 0; z < Z; z++) {
            float t = zrow[z] - emb[k * Z + z];
            d = fmaf(t, t, d);
        }
        zd[(long long)b * K + k] = d;
        float pk = powf(1.0f + d / 10.0f, -5.5f);   // T_DF=10 -> exponent -(T+1)/2
        p[k] = pk;
        sum += pk;
    }
    int best = 0;
    float bestv = -1.f;
    for (int k = 0; k < K; k++) {
        float v = p[k] / sum;
        dp[(long long)b * K + k] = v;
        if (v > bestv) { bestv = v; best = k; }   // first-max = jnp.argmax
    }
    kout[b] = (float)best;
    for (int z = 0; z < Z; z++) zq[(long long)b * Z + z] = emb[best * Z + z];
}

// Decoder hidden layers: h = relu(zrow @ W1 + b1) for both decoders.
// grid = (B, 2): y=0 -> e-decoder(z_e), y=1 -> q-decoder(z_q). blockDim = H.
__global__ void dec_h_kernel(const float* __restrict__ ze, const float* __restrict__ zq,
                             const float* __restrict__ we1, const float* __restrict__ be1,
                             const float* __restrict__ wq1, const float* __restrict__ bq1,
                             int B, int Z, int H)
{
    __shared__ float zrow[MAXZ];
    int b = blockIdx.x;
    int which = blockIdx.y;
    const float* zsrc = (which == 0) ? ze : zq;
    if (threadIdx.x < Z) zrow[threadIdx.x] = zsrc[(long long)b * Z + threadIdx.x];
    __syncthreads();

    int h = threadIdx.x;
    if (h >= H) return;
    const float* w1 = (which == 0) ? we1 : wq1;
    const float* b1 = (which == 0) ? be1 : bq1;
    float acc = b1[h];
    for (int k = 0; k < Z; k++) acc = fmaf(zrow[k], w1[k * H + h], acc);
    g_hd[(long long)which * B * H + (long long)b * H + h] = fmaxf(acc, 0.f);
}

// ---------------------------------------------------------------------------
extern "C" void kernel_launch(void* const* d_in, const int* in_sizes, int n_in,
                              void* d_out, int out_size)
{
    const float* x      = (const float*)d_in[0];
    const float* enc_w1 = (const float*)d_in[1];
    const float* enc_b1 = (const float*)d_in[2];
    const float* enc_w2 = (const float*)d_in[3];
    const float* enc_b2 = (const float*)d_in[4];
    const float* emb    = (const float*)d_in[5];
    const float* de_w1  = (const float*)d_in[6];
    const float* de_b1  = (const float*)d_in[7];
    const float* de_w2  = (const float*)d_in[8];
    const float* de_b2  = (const float*)d_in[9];
    const float* dq_w1  = (const float*)d_in[10];
    const float* dq_b1  = (const float*)d_in[11];
    const float* dq_w2  = (const float*)d_in[12];
    const float* dq_b2  = (const float*)d_in[13];

    const int H = in_sizes[2];
    const int Z = in_sizes[4];
    const int D = in_sizes[1] / H;
    const int B = in_sizes[0] / D;
    const int K = in_sizes[5] / Z;

    float* out = (float*)d_out;
    const long long BD = (long long)B * D;
    const long long BZ = (long long)B * Z;
    const long long BKll = (long long)B * K;
    float* o_xe = out;
    float* o_xq = out + BD;
    float* o_ze = out + 2 * BD;
    float* o_zq = out + 2 * BD + BZ;
    float* o_k  = out + 2 * BD + 2 * BZ;
    float* o_zd = o_k + B;
    float* o_dp = o_zd + BKll;
    (void)o_dp; (void)out_size; (void)n_in;

    float* p_part = nullptr;
    float* p_hd = nullptr;
    cudaGetSymbolAddress((void**)&p_part, g_part);
    cudaGetSymbolAddress((void**)&p_hd, g_hd);

    // --- Stage A: encoder GEMM1 (split-K=8), partials -> g_part ---
    {
        int chunk = (D + SPLITS - 1) / SPLITS;
        dim3 grid((H + 127) / 128, (B + 63) / 64, SPLITS);
        sgemm_kernel<64, 128, 16, 4, 8, false><<<grid, 256>>>(
            x, enc_w1, nullptr, p_part,
            B, H, /*lda=*/D, /*ldw=*/H, /*ldc=*/H,
            /*Kd=*/D, chunk, /*partStride=*/(long long)B * H);
    }
    // Reduce + bias + ReLU -> g_h1
    {
        int MH = B * H;
        h1_epilogue_kernel<<<(MH + 255) / 256, 256>>>(enc_b1, MH, H);
    }
    // --- Stage B: z_e ---
    zenc_kernel<<<(B * Z + 255) / 256, 256>>>(enc_w2, enc_b2, o_ze, B, H, Z);

    // --- Stage C: clustering outputs (z_dist, dist_prob, k, z_q) ---
    cluster_kernel<<<(B + 255) / 256, 256>>>(o_ze, emb, o_zq, o_k, o_zd, o_dp, B, Z, K);

    // --- Stage D: decoder hidden layers ---
    {
        dim3 grid(B, 2);
        dec_h_kernel<<<grid, H>>>(o_ze, o_zq, de_w1, de_b1, dq_w1, dq_b1, B, Z, H);
    }

    // --- Stage E: decoder output GEMMs (bias fused) ---
    {
        dim3 grid((D + 127) / 128, (B + 127) / 128, 1);
        sgemm_kernel<128, 128, 16, 8, 8, true><<<grid, 256>>>(
            p_hd, de_w2, de_b2, o_xe,
            B, D, /*lda=*/H, /*ldw=*/D, /*ldc=*/D,
            /*Kd=*/H, /*chunk=*/H, /*partStride=*/0);
        sgemm_kernel<128, 128, 16, 8, 8, true><<<grid, 256>>>(
            p_hd + (long long)B * H, dq_w2, dq_b2, o_xq,
            B, D, /*lda=*/H, /*ldw=*/D, /*ldc=*/D,
            /*Kd=*/H, /*chunk=*/H, /*partStride=*/0);
    }
}

// round 3
// speedup vs baseline: 2.7761x; 2.7761x over previous
#include <cuda_runtime.h>
#include <cuda_bf16.h>
#include <cstdint>
#include <math.h>

// ============================================================================
// AnnoCluster on GB300 (ptxas target is plain sm_103 -> no tcgen05).
// Engine: mma.sync.m16n8k16 bf16 (HMMA), 3-pass split precision:
//     C = Ah*Bh + Ah*Bl + Al*Bh     (bf16 hi/lo, fp32 accum)
// ============================================================================

#define SPLITS 8
#define BMAX 4096
#define HMAX 128
#define KP1MAX 10240   // D padded to 256 (=32*SPLITS) multiple
#define NP2MAX 10112   // D padded to 128 multiple

// ---- device scratch ----
__device__ float g_part[SPLITS * BMAX * HMAX];
__device__ float g_h1[BMAX * HMAX];
__device__ __nv_bfloat16 g_xh[BMAX * KP1MAX];
__device__ __nv_bfloat16 g_xl[BMAX * KP1MAX];
__device__ __nv_bfloat16 g_w1h[HMAX * KP1MAX];
__device__ __nv_bfloat16 g_w1l[HMAX * KP1MAX];
__device__ __nv_bfloat16 g_w2eh[NP2MAX * HMAX];
__device__ __nv_bfloat16 g_w2el[NP2MAX * HMAX];
__device__ __nv_bfloat16 g_w2qh[NP2MAX * HMAX];
__device__ __nv_bfloat16 g_w2ql[NP2MAX * HMAX];
__device__ __nv_bfloat16 g_hdh[2 * BMAX * HMAX];
__device__ __nv_bfloat16 g_hdl[2 * BMAX * HMAX];

// ============================================================================
// helpers
// ============================================================================
__device__ __forceinline__ uint32_t smem_u32(const void* p) {
    uint32_t a;
    asm("{ .reg .u64 t; cvta.to.shared.u64 t, %1; cvt.u32.u64 %0, t; }"
        : "=r"(a) : "l"(p));
    return a;
}
__device__ __forceinline__ void cp16(uint32_t dst, const void* src) {
    asm volatile("cp.async.cg.shared.global [%0], [%1], 16;"
                 :: "r"(dst), "l"(__cvta_generic_to_global(src)) : "memory");
}
#define CP_COMMIT() asm volatile("cp.async.commit_group;" ::: "memory")
#define CP_WAIT(n)  asm volatile("cp.async.wait_group %0;" :: "n"(n) : "memory")

__device__ __forceinline__ uint32_t lds32(uint32_t a) {
    uint32_t v;
    asm volatile("ld.shared.b32 %0, [%1];" : "=r"(v) : "r"(a));
    return v;
}

#define MMA_BF16(d, a, b) \
    asm volatile("mma.sync.aligned.m16n8k16.row.col.f32.bf16.bf16.f32 " \
                 "{%0,%1,%2,%3}, {%4,%5,%6,%7}, {%8,%9}, {%0,%1,%2,%3};" \
                 : "+f"((d)[0]), "+f"((d)[1]), "+f"((d)[2]), "+f"((d)[3]) \
                 : "r"((a)[0]), "r"((a)[1]), "r"((a)[2]), "r"((a)[3]), \
                   "r"((b)[0]), "r"((b)[1]))

__device__ __forceinline__ uint32_t pack_bf16(__nv_bfloat16 a, __nv_bfloat16 b) {
    return ((uint32_t)__bfloat16_as_ushort(b) << 16) | (uint32_t)__bfloat16_as_ushort(a);
}

// tile geometry: 128 rows x 32 bf16 cols, padded row stride 80B (conflict-free)
#define TROW 80
#define TILE_BYTES (128 * TROW)        // 10240
#define STAGES 3
#define STAGE_BYTES (4 * TILE_BYTES)   // Ah,Al,Bh,Bl
#define SMEM_TOTAL (STAGES * STAGE_BYTES)  // 122880

// ============================================================================
// mma.sync 3-pass split GEMM
//   A[M,*] hi/lo bf16 (lda), B[N,*] hi/lo bf16 K-major (ldb)
//   C[M tile 128 x N tile 128] fp32 (+bias), blockIdx.z = split-K slice
// All operand dims padded: no bounds checks in the mainloop.
// ============================================================================
__global__ __launch_bounds__(256, 1)
void mma_gemm_kernel(const __nv_bfloat16* __restrict__ Ah,
                     const __nv_bfloat16* __restrict__ Al,
                     const __nv_bfloat16* __restrict__ Bh,
                     const __nv_bfloat16* __restrict__ Bl,
                     const float* __restrict__ bias,
                     float* __restrict__ C,
                     int lda, int ldb, int ldc, int Nvalid,
                     int itersPerSplit, long long splitStride)
{
    extern __shared__ char smem[];
    const uint32_t sb = smem_u32(smem);
    const int tid = threadIdx.x;
    const int wid = tid >> 5;
    const int lid = tid & 31;
    const int mBase = blockIdx.y * 128;
    const int nBase = blockIdx.x * 128;
    C += (long long)blockIdx.z * splitStride;
    const int c0 = blockIdx.z * itersPerSplit;
    const int iters = itersPerSplit;

    // -------- stage loader: 4 tiles x 512 16B-chunks, 2 chunks/thread/tile --
    auto load_stage = [&](int s, int it) {
        const uint32_t dst = sb + (uint32_t)s * STAGE_BYTES;
        const int k0 = (c0 + it) * 32;
#pragma unroll
        for (int t = 0; t < 2; t++) {
            const int id = t * 256 + tid;
            const int r = id >> 2, c = id & 3;
            const uint32_t o = (uint32_t)r * TROW + (uint32_t)c * 16;
            const size_t aoff = (size_t)(mBase + r) * lda + k0 + c * 8;
            const size_t boff = (size_t)(nBase + r) * ldb + k0 + c * 8;
            cp16(dst + o,                  Ah + aoff);
            cp16(dst + TILE_BYTES + o,     Al + aoff);
            cp16(dst + 2 * TILE_BYTES + o, Bh + boff);
            cp16(dst + 3 * TILE_BYTES + o, Bl + boff);
        }
    };

    float acc[4][4][4];
#pragma unroll
    for (int i = 0; i < 4; i++)
#pragma unroll
        for (int j = 0; j < 4; j++)
#pragma unroll
            for (int q = 0; q < 4; q++) acc[i][j][q] = 0.f;

    // prologue
#pragma unroll
    for (int s = 0; s < STAGES - 1; s++) {
        load_stage(s, s);
        CP_COMMIT();
    }

    const int wm = (wid >> 2) * 64;
    const int wn = (wid & 3) * 32;
    const int lr = lid >> 2;
    const int lc = lid & 3;

    for (int i = 0; i < iters; i++) {
        CP_WAIT(STAGES - 2);
        __syncthreads();
        if (i + STAGES - 1 < iters) load_stage((i + STAGES - 1) % STAGES, i + STAGES - 1);
        CP_COMMIT();

        const uint32_t base = sb + (uint32_t)(i % STAGES) * STAGE_BYTES;
#pragma unroll
        for (int ks = 0; ks < 2; ks++) {
            const uint32_t ko = (uint32_t)ks * 32 + (uint32_t)lc * 4;
            uint32_t ar[4][4], alr[4][4], br[4][2], blr[4][2];
#pragma unroll
            for (int mi = 0; mi < 4; mi++) {
                const uint32_t a0 = base + (uint32_t)(wm + mi * 16 + lr) * TROW + ko;
                ar[mi][0] = lds32(a0);
                ar[mi][1] = lds32(a0 + 8 * TROW);
                ar[mi][2] = lds32(a0 + 16);
                ar[mi][3] = lds32(a0 + 8 * TROW + 16);
                const uint32_t a1 = a0 + TILE_BYTES;
                alr[mi][0] = lds32(a1);
                alr[mi][1] = lds32(a1 + 8 * TROW);
                alr[mi][2] = lds32(a1 + 16);
                alr[mi][3] = lds32(a1 + 8 * TROW + 16);
            }
#pragma unroll
            for (int ni = 0; ni < 4; ni++) {
                const uint32_t b0 = base + 2 * TILE_BYTES +
                                    (uint32_t)(wn + ni * 8 + lr) * TROW + ko;
                br[ni][0] = lds32(b0);
                br[ni][1] = lds32(b0 + 16);
                blr[ni][0] = lds32(b0 + TILE_BYTES);
                blr[ni][1] = lds32(b0 + TILE_BYTES + 16);
            }
#pragma unroll
            for (int mi = 0; mi < 4; mi++)
#pragma unroll
                for (int ni = 0; ni < 4; ni++) {
                    MMA_BF16(acc[mi][ni], ar[mi], br[ni]);
                    MMA_BF16(acc[mi][ni], ar[mi], blr[ni]);
                    MMA_BF16(acc[mi][ni], alr[mi], br[ni]);
                }
        }
    }
    CP_WAIT(0);

    // epilogue: direct reg -> gmem (float2 pairs)
#pragma unroll
    for (int mi = 0; mi < 4; mi++) {
        const int r0 = mBase + wm + mi * 16 + lr;
#pragma unroll
        for (int ni = 0; ni < 4; ni++) {
            const int c = nBase + wn + ni * 8 + lc * 2;
            if (c < Nvalid) {
                float b0 = 0.f, b1 = 0.f;
                if (bias) { b0 = bias[c]; b1 = bias[c + 1]; }
                float2 v0 = make_float2(acc[mi][ni][0] + b0, acc[mi][ni][1] + b1);
                float2 v1 = make_float2(acc[mi][ni][2] + b0, acc[mi][ni][3] + b1);
                *(float2*)&C[(long long)r0 * ldc + c] = v0;
                *(float2*)&C[(long long)(r0 + 8) * ldc + c] = v1;
            }
        }
    }
}

// ============================================================================
// x fp32 -> bf16 hi/lo, padded [B, KP]
// ============================================================================
__global__ void convx_kernel(const float* __restrict__ x,
                             __nv_bfloat16* __restrict__ xh,
                             __nv_bfloat16* __restrict__ xl,
                             int B, int D, int KP)
{
    const int per = KP / 4;
    int idx = blockIdx.x * blockDim.x + threadIdx.x;
    if (idx >= B * per) return;
    const int b = idx / per;
    const int c = (idx % per) * 4;
    float4 v = make_float4(0.f, 0.f, 0.f, 0.f);
    if (c + 4 <= D) v = *(const float4*)(x + (size_t)b * D + c);
    __nv_bfloat16 h0 = __float2bfloat16(v.x), h1 = __float2bfloat16(v.y);
    __nv_bfloat16 h2 = __float2bfloat16(v.z), h3 = __float2bfloat16(v.w);
    __nv_bfloat16 l0 = __float2bfloat16(v.x - __bfloat162float(h0));
    __nv_bfloat16 l1 = __float2bfloat16(v.y - __bfloat162float(h1));
    __nv_bfloat16 l2 = __float2bfloat16(v.z - __bfloat162float(h2));
    __nv_bfloat16 l3 = __float2bfloat16(v.w - __bfloat162float(h3));
    const size_t o = (size_t)b * KP + c;
    *(uint2*)(xh + o) = make_uint2(pack_bf16(h0, h1), pack_bf16(h2, h3));
    *(uint2*)(xl + o) = make_uint2(pack_bf16(l0, l1), pack_bf16(l2, l3));
}

// ============================================================================
// transpose + bf16 hi/lo split: in[K,N] fp32 -> oh/ol [Npad, Kpad] bf16
// ============================================================================
__global__ void transpose_split_kernel(const float* __restrict__ in,
                                       __nv_bfloat16* __restrict__ oh,
                                       __nv_bfloat16* __restrict__ ol,
                                       int K, int N, int Kpad, int Npad)
{
    __shared__ float t[32][33];
    const int k0 = blockIdx.x * 32, n0 = blockIdx.y * 32;
    for (int i = threadIdx.y; i < 32; i += 8) {
        int k = k0 + i, n = n0 + threadIdx.x;
        t[i][threadIdx.x] = (k < K && n < N) ? in[(size_t)k * N + n] : 0.f;
    }
    __syncthreads();
    for (int i = threadIdx.y; i < 32; i += 8) {
        int n = n0 + i, k = k0 + threadIdx.x;
        if (n < Npad && k < Kpad) {
            float v = t[threadIdx.x][i];
            __nv_bfloat16 h = __float2bfloat16(v);
            oh[(size_t)n * Kpad + k] = h;
            ol[(size_t)n * Kpad + k] = __float2bfloat16(v - __bfloat162float(h));
        }
    }
}

// ============================================================================
// small fused kernels
// ============================================================================
__global__ void h1_epilogue_kernel(const float* __restrict__ bias, int MH, int H)
{
    int i = blockIdx.x * blockDim.x + threadIdx.x;
    if (i >= MH) return;
    float s = 0.f;
#pragma unroll
    for (int p = 0; p < SPLITS; p++) s += g_part[(long long)p * MH + i];
    s += bias[i % H];
    g_h1[i] = fmaxf(s, 0.f);
}

__global__ void zenc_kernel(const float* __restrict__ w2, const float* __restrict__ b2,
                            float* __restrict__ ze, int B, int H, int Z)
{
    int t = blockIdx.x * blockDim.x + threadIdx.x;
    if (t >= B * Z) return;
    int b = t / Z, z = t % Z;
    const float* h1 = g_h1 + (long long)b * H;
    float acc = b2[z];
    for (int k = 0; k < H; k++) acc = fmaf(h1[k], w2[k * Z + z], acc);
    ze[t] = acc;
}

#define MAXZ 64
#define MAXKC 64
__global__ void cluster_kernel(const float* __restrict__ ze, const float* __restrict__ emb,
                               float* __restrict__ zq, float* __restrict__ kout,
                               float* __restrict__ zd, float* __restrict__ dp,
                               int B, int Z, int K)
{
    int b = blockIdx.x * blockDim.x + threadIdx.x;
    if (b >= B) return;

    float zrow[MAXZ];
    for (int z = 0; z < Z; z++) zrow[z] = ze[(long long)b * Z + z];

    float p[MAXKC];
    float sum = 0.f;
    for (int k = 0; k < K; k++) {
        float d = 0.f;
        for (int z = 0; z < Z; z++) {
            float t = zrow[z] - emb[k * Z + z];
            d = fmaf(t, t, d);
        }
        zd[(long long)b * K + k] = d;
        float pk = powf(1.0f + d * 0.1f, -5.5f);   // T_DF=10 -> -(T+1)/2
        p[k] = pk;
        sum += pk;
    }
    float inv = 1.0f / sum;
    int best = 0;
    float bestv = -1.f;
    for (int k = 0; k < K; k++) {
        float v = p[k] * inv;
        dp[(long long)b * K + k] = v;
        if (v > bestv) { bestv = v; best = k; }
    }
    kout[b] = (float)best;
    for (int z = 0; z < Z; z++) zq[(long long)b * Z + z] = emb[best * Z + z];
}

__global__ void dec_h_kernel(const float* __restrict__ ze, const float* __restrict__ zq,
                             const float* __restrict__ we1, const float* __restrict__ be1,
                             const float* __restrict__ wq1, const float* __restrict__ bq1,
                             int B, int Z, int H)
{
    __shared__ float zrow[MAXZ];
    int b = blockIdx.x;
    int which = blockIdx.y;
    const float* zsrc = (which == 0) ? ze : zq;
    if (threadIdx.x < Z) zrow[threadIdx.x] = zsrc[(long long)b * Z + threadIdx.x];
    __syncthreads();

    int h = threadIdx.x;
    if (h >= H) return;
    const float* w1 = (which == 0) ? we1 : wq1;
    const float* b1 = (which == 0) ? be1 : bq1;
    float acc = b1[h];
    for (int k = 0; k < Z; k++) acc = fmaf(zrow[k], w1[k * H + h], acc);
    float v = fmaxf(acc, 0.f);
    long long idx = (long long)which * B * H + (long long)b * H + h;
    __nv_bfloat16 hi = __float2bfloat16(v);
    g_hdh[idx] = hi;
    g_hdl[idx] = __float2bfloat16(v - __bfloat162float(hi));
}

// ============================================================================
extern "C" void kernel_launch(void* const* d_in, const int* in_sizes, int n_in,
                              void* d_out, int out_size)
{
    const float* x      = (const float*)d_in[0];
    const float* enc_w1 = (const float*)d_in[1];
    const float* enc_b1 = (const float*)d_in[2];
    const float* enc_w2 = (const float*)d_in[3];
    const float* enc_b2 = (const float*)d_in[4];
    const float* emb    = (const float*)d_in[5];
    const float* de_w1  = (const float*)d_in[6];
    const float* de_b1  = (const float*)d_in[7];
    const float* de_w2  = (const float*)d_in[8];
    const float* de_b2  = (const float*)d_in[9];
    const float* dq_w1  = (const float*)d_in[10];
    const float* dq_b1  = (const float*)d_in[11];
    const float* dq_w2  = (const float*)d_in[12];
    const float* dq_b2  = (const float*)d_in[13];

    const int H = in_sizes[2];
    const int Z = in_sizes[4];
    const int D = in_sizes[1] / H;
    const int B = in_sizes[0] / D;
    const int K = in_sizes[5] / Z;

    const int KP1 = ((D + 255) / 256) * 256;    // 10240 (multiple of 32*SPLITS)
    const int NT2 = (D + 127) / 128;            // 79
    const int NP2 = NT2 * 128;                  // 10112

    float* out = (float*)d_out;
    const long long BD = (long long)B * D;
    const long long BZ = (long long)B * Z;
    float* o_xe = out;
    float* o_xq = out + BD;
    float* o_ze = out + 2 * BD;
    float* o_zq = out + 2 * BD + BZ;
    float* o_k  = out + 2 * BD + 2 * BZ;
    float* o_zd = o_k + B;
    float* o_dp = o_zd + (long long)B * K;
    (void)out_size; (void)n_in;

    float* p_part;
    __nv_bfloat16 *p_xh, *p_xl, *p_w1h, *p_w1l;
    __nv_bfloat16 *p_w2eh, *p_w2el, *p_w2qh, *p_w2ql, *p_hdh, *p_hdl;
    cudaGetSymbolAddress((void**)&p_part, g_part);
    cudaGetSymbolAddress((void**)&p_xh, g_xh);
    cudaGetSymbolAddress((void**)&p_xl, g_xl);
    cudaGetSymbolAddress((void**)&p_w1h, g_w1h);
    cudaGetSymbolAddress((void**)&p_w1l, g_w1l);
    cudaGetSymbolAddress((void**)&p_w2eh, g_w2eh);
    cudaGetSymbolAddress((void**)&p_w2el, g_w2el);
    cudaGetSymbolAddress((void**)&p_w2qh, g_w2qh);
    cudaGetSymbolAddress((void**)&p_w2ql, g_w2ql);
    cudaGetSymbolAddress((void**)&p_hdh, g_hdh);
    cudaGetSymbolAddress((void**)&p_hdl, g_hdl);

    cudaFuncSetAttribute(mma_gemm_kernel,
                         cudaFuncAttributeMaxDynamicSharedMemorySize, SMEM_TOTAL);

    // --- operand prep: x split + weight transposes/splits ---
    {
        int n4 = B * (KP1 / 4);
        convx_kernel<<<(n4 + 255) / 256, 256>>>(x, p_xh, p_xl, B, D, KP1);
        dim3 blk(32, 8);
        dim3 g1((KP1 + 31) / 32, (H + 31) / 32);
        transpose_split_kernel<<<g1, blk>>>(enc_w1, p_w1h, p_w1l, D, H, KP1, H);
        dim3 g2((H + 31) / 32, (NP2 + 31) / 32);
        transpose_split_kernel<<<g2, blk>>>(de_w2, p_w2eh, p_w2el, H, D, H, NP2);
        transpose_split_kernel<<<g2, blk>>>(dq_w2, p_w2qh, p_w2ql, H, D, H, NP2);
    }

    // --- encoder GEMM1: x[B,KP1] @ w1t[128,KP1]^T, split-K=8 -> partials ---
    {
        dim3 grid(1, B / 128, SPLITS);
        mma_gemm_kernel<<<grid, 256, SMEM_TOTAL>>>(
            p_xh, p_xl, p_w1h, p_w1l, nullptr, p_part,
            /*lda=*/KP1, /*ldb=*/KP1, /*ldc=*/H, /*Nvalid=*/H,
            /*itersPerSplit=*/(KP1 / 32) / SPLITS,
            /*splitStride=*/(long long)B * H);
    }
    h1_epilogue_kernel<<<(B * H + 255) / 256, 256>>>(enc_b1, B * H, H);

    // --- z_e, clustering, decoder hiddens ---
    zenc_kernel<<<(B * Z + 255) / 256, 256>>>(enc_w2, enc_b2, o_ze, B, H, Z);
    cluster_kernel<<<(B + 63) / 64, 64>>>(o_ze, emb, o_zq, o_k, o_zd, o_dp, B, Z, K);
    {
        dim3 grid(B, 2);
        dec_h_kernel<<<grid, H>>>(o_ze, o_zq, de_w1, de_b1, dq_w1, dq_b1, B, Z, H);
    }

    // --- decoder output GEMMs: hd[B,H] @ w2t[NP2,H]^T + bias ---
    {
        dim3 grid(NT2, B / 128, 1);
        mma_gemm_kernel<<<grid, 256, SMEM_TOTAL>>>(
            p_hdh, p_hdl, p_w2eh, p_w2el, de_b2, o_xe,
            /*lda=*/H, /*ldb=*/H, /*ldc=*/D, /*Nvalid=*/D,
            /*itersPerSplit=*/H / 32, /*splitStride=*/0);
        mma_gemm_kernel<<<grid, 256, SMEM_TOTAL>>>(
            p_hdh + (long long)B * H, p_hdl + (long long)B * H,
            p_w2qh, p_w2ql, dq_b2, o_xq,
            /*lda=*/H, /*ldb=*/H, /*ldc=*/D, /*Nvalid=*/D,
            /*itersPerSplit=*/H / 32, /*splitStride=*/0);
    }
}

// round 4
// speedup vs baseline: 3.4955x; 1.2591x over previous
#include <cuda_runtime.h>
#include <cuda_bf16.h>
#include <cstdint>
#include <math.h>

// ============================================================================
// AnnoCluster on GB300 (plain sm_103 target -> mma.sync HMMA path).
// 3-pass split precision: C = Ah*Bh + Ah*Bl + Al*Bh  (bf16 hi/lo, fp32 accum)
// R4: fused x-conversion in encoder GEMM, 2 CTA/SM (2-stage smem),
//     ldmatrix fragment loads, smem-staged coalesced epilogue.
// ============================================================================

#define SPLITS 8
#define BMAX 4096
#define HMAX 128
#define KP1MAX 10240
#define NP2MAX 10112

__device__ float g_part[SPLITS * BMAX * HMAX];
__device__ float g_h1[BMAX * HMAX];
__device__ __nv_bfloat16 g_w1h[HMAX * KP1MAX];
__device__ __nv_bfloat16 g_w1l[HMAX * KP1MAX];
__device__ __nv_bfloat16 g_w2eh[NP2MAX * HMAX];
__device__ __nv_bfloat16 g_w2el[NP2MAX * HMAX];
__device__ __nv_bfloat16 g_w2qh[NP2MAX * HMAX];
__device__ __nv_bfloat16 g_w2ql[NP2MAX * HMAX];
__device__ __nv_bfloat16 g_hdh[2 * BMAX * HMAX];
__device__ __nv_bfloat16 g_hdl[2 * BMAX * HMAX];

// ============================================================================
// helpers
// ============================================================================
__device__ __forceinline__ uint32_t smem_u32(const void* p) {
    uint32_t a;
    asm("{ .reg .u64 t; cvta.to.shared.u64 t, %1; cvt.u32.u64 %0, t; }"
        : "=r"(a) : "l"(p));
    return a;
}
__device__ __forceinline__ void cp16(uint32_t dst, const void* src) {
    asm volatile("cp.async.cg.shared.global [%0], [%1], 16;"
                 :: "r"(dst), "l"(__cvta_generic_to_global(src)) : "memory");
}
#define CP_COMMIT() asm volatile("cp.async.commit_group;" ::: "memory")
#define CP_WAIT(n)  asm volatile("cp.async.wait_group %0;" :: "n"(n) : "memory")

#define LDMX4(r0, r1, r2, r3, a) \
    asm volatile("ldmatrix.sync.aligned.m8n8.x4.shared.b16 {%0,%1,%2,%3}, [%4];" \
                 : "=r"(r0), "=r"(r1), "=r"(r2), "=r"(r3) : "r"(a))

#define MMA_BF16(d, a, b) \
    asm volatile("mma.sync.aligned.m16n8k16.row.col.f32.bf16.bf16.f32 " \
                 "{%0,%1,%2,%3}, {%4,%5,%6,%7}, {%8,%9}, {%0,%1,%2,%3};" \
                 : "+f"((d)[0]), "+f"((d)[1]), "+f"((d)[2]), "+f"((d)[3]) \
                 : "r"((a)[0]), "r"((a)[1]), "r"((a)[2]), "r"((a)[3]), \
                   "r"((b)[0]), "r"((b)[1]))

__device__ __forceinline__ void sts128(uint32_t a, uint32_t x, uint32_t y,
                                       uint32_t z, uint32_t w) {
    asm volatile("st.shared.v4.b32 [%0], {%1, %2, %3, %4};"
                 :: "r"(a), "r"(x), "r"(y), "r"(z), "r"(w) : "memory");
}

__device__ __forceinline__ uint32_t pack_bf16(__nv_bfloat16 a, __nv_bfloat16 b) {
    return ((uint32_t)__bfloat16_as_ushort(b) << 16) | (uint32_t)__bfloat16_as_ushort(a);
}

// tile: 128 rows x 32 bf16 (64B data + 16B pad per row)
#define TROW 80
#define TILE_BYTES (128 * TROW)            // 10240
#define STAGE_BYTES (4 * TILE_BYTES)       // Ah, Al, Bh, Bl
#define SMEM_TOTAL (2 * STAGE_BYTES)       // 81920 (2 stages -> 2 CTA/SM)

// ============================================================================
// mma.sync 3-pass split GEMM, 128x128 C tile, 8 warps (2x4 of 64x32)
//   CONVA=true: A is fp32 (lda = D); conversion fused in loader.
//   CONVA=false: A given as bf16 hi/lo (lda).
//   B: bf16 hi/lo K-major [N, ldb]. blockIdx.z = split-K slice.
// ============================================================================
template <bool CONVA>
__global__ __launch_bounds__(256, 2)
void mma_gemm_kernel(const float* __restrict__ Afp,
                     const __nv_bfloat16* __restrict__ Ah,
                     const __nv_bfloat16* __restrict__ Al,
                     const __nv_bfloat16* __restrict__ Bh,
                     const __nv_bfloat16* __restrict__ Bl,
                     const float* __restrict__ bias,
                     float* __restrict__ C,
                     int lda, int ldb, int ldc, int Nvalid, int Dvalid,
                     int itersPerSplit, long long splitStride)
{
    extern __shared__ char smem[];
    const uint32_t sb = smem_u32(smem);
    const int tid = threadIdx.x;
    const int wid = tid >> 5;
    const int lid = tid & 31;
    const int mBase = blockIdx.y * 128;
    const int nBase = blockIdx.x * 128;
    C += (long long)blockIdx.z * splitStride;
    const int c0 = blockIdx.z * itersPerSplit;
    const int iters = itersPerSplit;

    // ---- B-stage loader via cp.async (and A when !CONVA) ----
    auto load_stage_async = [&](int s, int it) {
        const uint32_t dst = sb + (uint32_t)s * STAGE_BYTES;
        const int k0 = (c0 + it) * 32;
#pragma unroll
        for (int t = 0; t < 2; t++) {
            const int id = t * 256 + tid;
            const int r = id >> 2, c = id & 3;
            const uint32_t o = (uint32_t)r * TROW + (uint32_t)c * 16;
            const size_t boff = (size_t)(nBase + r) * ldb + k0 + c * 8;
            cp16(dst + 2 * TILE_BYTES + o, Bh + boff);
            cp16(dst + 3 * TILE_BYTES + o, Bl + boff);
            if (!CONVA) {
                const size_t aoff = (size_t)(mBase + r) * lda + k0 + c * 8;
                cp16(dst + o,              Ah + aoff);
                cp16(dst + TILE_BYTES + o, Al + aoff);
            }
        }
    };

    // ---- fp32 A prefetch (CONVA): 16 floats/thread ----
    const int ar_ = tid >> 1;          // row 0..127
    const int ah_ = tid & 1;           // k half (16 floats)
    float4 pre[4];
    auto ldg_a = [&](int it) {
        const int k0 = (c0 + it) * 32 + ah_ * 16;
        const float* base = Afp + (size_t)(mBase + ar_) * lda;
#pragma unroll
        for (int q = 0; q < 4; q++) {
            const int gk = k0 + q * 4;
            if (gk + 4 <= Dvalid) {
                pre[q] = *(const float4*)(base + gk);
            } else {
                float4 v = make_float4(0.f, 0.f, 0.f, 0.f);
                if (gk < Dvalid) {
                    v.x = base[gk];
                    if (gk + 1 < Dvalid) v.y = base[gk + 1];
                    if (gk + 2 < Dvalid) v.z = base[gk + 2];
                }
                pre[q] = v;
            }
        }
    };
    auto sts_a = [&](int s) {
        const uint32_t dst = sb + (uint32_t)s * STAGE_BYTES +
                             (uint32_t)ar_ * TROW + (uint32_t)ah_ * 32;
        uint32_t hi[4], lo[4];
#pragma unroll
        for (int q = 0; q < 4; q++) {
            const float fx = pre[q].x, fy = pre[q].y, fz = pre[q].z, fw = pre[q].w;
            __nv_bfloat16 h0 = __float2bfloat16(fx), h1 = __float2bfloat16(fy);
            __nv_bfloat16 h2 = __float2bfloat16(fz), h3 = __float2bfloat16(fw);
            hi[q] = pack_bf16(h0, h1);  // only first 2 used per q pair; pack 4 below
            __nv_bfloat16 l0 = __float2bfloat16(fx - __bfloat162float(h0));
            __nv_bfloat16 l1 = __float2bfloat16(fy - __bfloat162float(h1));
            lo[q] = pack_bf16(l0, l1);
            // second pair
            __nv_bfloat16 l2 = __float2bfloat16(fz - __bfloat162float(h2));
            __nv_bfloat16 l3 = __float2bfloat16(fw - __bfloat162float(h3));
            // stash via shared arrays below
            pre[q].x = __uint_as_float(pack_bf16(h2, h3));
            pre[q].y = __uint_as_float(pack_bf16(l2, l3));
        }
        // layout per q: hi[q] (k 4q..4q+1), pre[q].x (k 4q+2..4q+3)
        sts128(dst,       hi[0], __float_as_uint(pre[0].x), hi[1], __float_as_uint(pre[1].x));
        sts128(dst + 16,  hi[2], __float_as_uint(pre[2].x), hi[3], __float_as_uint(pre[3].x));
        sts128(dst + TILE_BYTES,      lo[0], __float_as_uint(pre[0].y), lo[1], __float_as_uint(pre[1].y));
        sts128(dst + TILE_BYTES + 16, lo[2], __float_as_uint(pre[2].y), lo[3], __float_as_uint(pre[3].y));
    };

    float acc[4][4][4];
#pragma unroll
    for (int i = 0; i < 4; i++)
#pragma unroll
        for (int j = 0; j < 4; j++)
#pragma unroll
            for (int q = 0; q < 4; q++) acc[i][j][q] = 0.f;

    // warp tiling
    const int wm = (wid >> 2) * 64;
    const int wn = (wid & 3) * 32;
    const int lr = lid >> 2;
    const int lc = lid & 3;

    // ldmatrix lane addressing
    const int a_row = lid & 15;          // m within 16
    const int a_kh  = (lid >> 4) * 16;   // byte offset for k-half
    const int b_grp = lid >> 3;          // 0..3
    const int b_row = lid & 7;
    const int b_nof = (b_grp >> 1) * 8;  // n sub-block
    const int b_kh  = (b_grp & 1) * 16;

    // prologue
    load_stage_async(0, 0);
    CP_COMMIT();
    if (CONVA) ldg_a(0);

    for (int i = 0; i < iters; i++) {
        const int buf = i & 1;
        if (CONVA) sts_a(buf);                       // A(i) regs -> smem
        if (i + 1 < iters) { load_stage_async(buf ^ 1, i + 1); CP_COMMIT(); }
        if (i + 1 < iters) { CP_WAIT(1); } else { CP_WAIT(0); }
        __syncthreads();
        if (CONVA && i + 1 < iters) ldg_a(i + 1);    // prefetch under MMA

        const uint32_t base = sb + (uint32_t)buf * STAGE_BYTES;
#pragma unroll
        for (int ks = 0; ks < 2; ks++) {
            const uint32_t ko = (uint32_t)ks * 32;
            // B fragments: 2 ldmatrix.x4 per (hi/lo) -> bh[2][4], bl[2][4]
            uint32_t bh[2][4], bl[2][4];
#pragma unroll
            for (int n2 = 0; n2 < 2; n2++) {
                const uint32_t baddr = base + 2 * TILE_BYTES +
                    (uint32_t)(wn + n2 * 16 + b_nof + b_row) * TROW + ko + b_kh;
                LDMX4(bh[n2][0], bh[n2][1], bh[n2][2], bh[n2][3], baddr);
                LDMX4(bl[n2][0], bl[n2][1], bl[n2][2], bl[n2][3], baddr + TILE_BYTES);
            }
#pragma unroll
            for (int mi = 0; mi < 4; mi++) {
                const uint32_t aaddr = base +
                    (uint32_t)(wm + mi * 16 + a_row) * TROW + ko + a_kh;
                uint32_t a[4], al4[4];
                LDMX4(a[0], a[1], a[2], a[3], aaddr);
                LDMX4(al4[0], al4[1], al4[2], al4[3], aaddr + TILE_BYTES);
#pragma unroll
                for (int n2 = 0; n2 < 2; n2++) {
#pragma unroll
                    for (int w = 0; w < 2; w++) {
                        float* d = acc[mi][n2 * 2 + w];
                        MMA_BF16(d, a,   (bh[n2] + w * 2));
                        MMA_BF16(d, a,   (bl[n2] + w * 2));
                        MMA_BF16(d, al4, (bh[n2] + w * 2));
                    }
                }
            }
        }
        __syncthreads();
    }
    CP_WAIT(0);

    // ---- epilogue: regs -> smem stage (129-pad) -> coalesced global ----
    float* stage = (float*)smem;
#pragma unroll
    for (int mi = 0; mi < 4; mi++) {
        const int r0 = wm + mi * 16 + lr;
#pragma unroll
        for (int ni = 0; ni < 4; ni++) {
            const int c = wn + ni * 8 + lc * 2;
            stage[r0 * 129 + c]           = acc[mi][ni][0];
            stage[r0 * 129 + c + 1]       = acc[mi][ni][1];
            stage[(r0 + 8) * 129 + c]     = acc[mi][ni][2];
            stage[(r0 + 8) * 129 + c + 1] = acc[mi][ni][3];
        }
    }
    __syncthreads();
#pragma unroll 4
    for (int idx = tid; idx < 128 * 128; idx += 256) {
        const int r = idx >> 7, c = idx & 127;
        const int n = nBase + c;
        if (n < Nvalid) {
            float v = stage[r * 129 + c];
            if (bias) v += bias[n];
            C[(long long)(mBase + r) * ldc + n] = v;
        }
    }
}

// ============================================================================
// transpose + bf16 hi/lo split: in[K,N] fp32 -> oh/ol [Npad, Kpad]
// ============================================================================
__global__ void transpose_split_kernel(const float* __restrict__ in,
                                       __nv_bfloat16* __restrict__ oh,
                                       __nv_bfloat16* __restrict__ ol,
                                       int K, int N, int Kpad, int Npad)
{
    __shared__ float t[32][33];
    const int k0 = blockIdx.x * 32, n0 = blockIdx.y * 32;
    for (int i = threadIdx.y; i < 32; i += 8) {
        int k = k0 + i, n = n0 + threadIdx.x;
        t[i][threadIdx.x] = (k < K && n < N) ? in[(size_t)k * N + n] : 0.f;
    }
    __syncthreads();
    for (int i = threadIdx.y; i < 32; i += 8) {
        int n = n0 + i, k = k0 + threadIdx.x;
        if (n < Npad && k < Kpad) {
            float v = t[threadIdx.x][i];
            __nv_bfloat16 h = __float2bfloat16(v);
            oh[(size_t)n * Kpad + k] = h;
            ol[(size_t)n * Kpad + k] = __float2bfloat16(v - __bfloat162float(h));
        }
    }
}

// ============================================================================
// small fused kernels
// ============================================================================
__global__ void h1_epilogue_kernel(const float* __restrict__ bias, int MH, int H)
{
    int i = blockIdx.x * blockDim.x + threadIdx.x;
    if (i >= MH) return;
    float s = 0.f;
#pragma unroll
    for (int p = 0; p < SPLITS; p++) s += g_part[(long long)p * MH + i];
    s += bias[i % H];
    g_h1[i] = fmaxf(s, 0.f);
}

__global__ void zenc_kernel(const float* __restrict__ w2, const float* __restrict__ b2,
                            float* __restrict__ ze, int B, int H, int Z)
{
    int t = blockIdx.x * blockDim.x + threadIdx.x;
    if (t >= B * Z) return;
    int b = t / Z, z = t % Z;
    const float* h1 = g_h1 + (long long)b * H;
    float acc = b2[z];
    for (int k = 0; k < H; k++) acc = fmaf(h1[k], w2[k * Z + z], acc);
    ze[t] = acc;
}

#define MAXZ 64
#define MAXKC 64
__global__ void cluster_kernel(const float* __restrict__ ze, const float* __restrict__ emb,
                               float* __restrict__ zq, float* __restrict__ kout,
                               float* __restrict__ zd, float* __restrict__ dp,
                               int B, int Z, int K)
{
    int b = blockIdx.x * blockDim.x + threadIdx.x;
    if (b >= B) return;

    float zrow[MAXZ];
    for (int z = 0; z < Z; z++) zrow[z] = ze[(long long)b * Z + z];

    float p[MAXKC];
    float sum = 0.f;
    for (int k = 0; k < K; k++) {
        float d = 0.f;
        for (int z = 0; z < Z; z++) {
            float t = zrow[z] - emb[k * Z + z];
            d = fmaf(t, t, d);
        }
        zd[(long long)b * K + k] = d;
        float pk = __powf(1.0f + d * 0.1f, -5.5f);   // T_DF=10 -> -(T+1)/2
        p[k] = pk;
        sum += pk;
    }
    float inv = 1.0f / sum;
    int best = 0;
    float bestv = -1.f;
    for (int k = 0; k < K; k++) {
        float v = p[k] * inv;
        dp[(long long)b * K + k] = v;
        if (v > bestv) { bestv = v; best = k; }
    }
    kout[b] = (float)best;
    for (int z = 0; z < Z; z++) zq[(long long)b * Z + z] = emb[best * Z + z];
}

__global__ void dec_h_kernel(const float* __restrict__ ze, const float* __restrict__ zq,
                             const float* __restrict__ we1, const float* __restrict__ be1,
                             const float* __restrict__ wq1, const float* __restrict__ bq1,
                             int B, int Z, int H)
{
    __shared__ float zrow[MAXZ];
    int b = blockIdx.x;
    int which = blockIdx.y;
    const float* zsrc = (which == 0) ? ze : zq;
    if (threadIdx.x < Z) zrow[threadIdx.x] = zsrc[(long long)b * Z + threadIdx.x];
    __syncthreads();

    int h = threadIdx.x;
    if (h >= H) return;
    const float* w1 = (which == 0) ? we1 : wq1;
    const float* b1 = (which == 0) ? be1 : bq1;
    float acc = b1[h];
    for (int k = 0; k < Z; k++) acc = fmaf(zrow[k], w1[k * H + h], acc);
    float v = fmaxf(acc, 0.f);
    long long idx = (long long)which * B * H + (long long)b * H + h;
    __nv_bfloat16 hi = __float2bfloat16(v);
    g_hdh[idx] = hi;
    g_hdl[idx] = __float2bfloat16(v - __bfloat162float(hi));
}

// ============================================================================
extern "C" void kernel_launch(void* const* d_in, const int* in_sizes, int n_in,
                              void* d_out, int out_size)
{
    const float* x      = (const float*)d_in[0];
    const float* enc_w1 = (const float*)d_in[1];
    const float* enc_b1 = (const float*)d_in[2];
    const float* enc_w2 = (const float*)d_in[3];
    const float* enc_b2 = (const float*)d_in[4];
    const float* emb    = (const float*)d_in[5];
    const float* de_w1  = (const float*)d_in[6];
    const float* de_b1  = (const float*)d_in[7];
    const float* de_w2  = (const float*)d_in[8];
    const float* de_b2  = (const float*)d_in[9];
    const float* dq_w1  = (const float*)d_in[10];
    const float* dq_b1  = (const float*)d_in[11];
    const float* dq_w2  = (const float*)d_in[12];
    const float* dq_b2  = (const float*)d_in[13];

    const int H = in_sizes[2];
    const int Z = in_sizes[4];
    const int D = in_sizes[1] / H;
    const int B = in_sizes[0] / D;
    const int K = in_sizes[5] / Z;

    const int KP1 = ((D + 255) / 256) * 256;    // 10240
    const int NT2 = (D + 127) / 128;            // 79
    const int NP2 = NT2 * 128;                  // 10112

    float* out = (float*)d_out;
    const long long BD = (long long)B * D;
    const long long BZ = (long long)B * Z;
    float* o_xe = out;
    float* o_xq = out + BD;
    float* o_ze = out + 2 * BD;
    float* o_zq = out + 2 * BD + BZ;
    float* o_k  = out + 2 * BD + 2 * BZ;
    float* o_zd = o_k + B;
    float* o_dp = o_zd + (long long)B * K;
    (void)out_size; (void)n_in;

    float* p_part;
    __nv_bfloat16 *p_w1h, *p_w1l;
    __nv_bfloat16 *p_w2eh, *p_w2el, *p_w2qh, *p_w2ql, *p_hdh, *p_hdl;
    cudaGetSymbolAddress((void**)&p_part, g_part);
    cudaGetSymbolAddress((void**)&p_w1h, g_w1h);
    cudaGetSymbolAddress((void**)&p_w1l, g_w1l);
    cudaGetSymbolAddress((void**)&p_w2eh, g_w2eh);
    cudaGetSymbolAddress((void**)&p_w2el, g_w2el);
    cudaGetSymbolAddress((void**)&p_w2qh, g_w2qh);
    cudaGetSymbolAddress((void**)&p_w2ql, g_w2ql);
    cudaGetSymbolAddress((void**)&p_hdh, g_hdh);
    cudaGetSymbolAddress((void**)&p_hdl, g_hdl);

    cudaFuncSetAttribute(mma_gemm_kernel<true>,
                         cudaFuncAttributeMaxDynamicSharedMemorySize, SMEM_TOTAL);
    cudaFuncSetAttribute(mma_gemm_kernel<false>,
                         cudaFuncAttributeMaxDynamicSharedMemorySize, SMEM_TOTAL);

    // --- weight prep: transpose to K-major + hi/lo split ---
    {
        dim3 blk(32, 8);
        dim3 g1((KP1 + 31) / 32, (H + 31) / 32);
        transpose_split_kernel<<<g1, blk>>>(enc_w1, p_w1h, p_w1l, D, H, KP1, H);
        dim3 g2((H + 31) / 32, (NP2 + 31) / 32);
        transpose_split_kernel<<<g2, blk>>>(de_w2, p_w2eh, p_w2el, H, D, H, NP2);
        transpose_split_kernel<<<g2, blk>>>(dq_w2, p_w2qh, p_w2ql, H, D, H, NP2);
    }

    // --- encoder GEMM1: x fp32 (fused split) @ w1t, split-K=8 -> partials ---
    {
        dim3 grid(1, B / 128, SPLITS);
        mma_gemm_kernel<true><<<grid, 256, SMEM_TOTAL>>>(
            x, nullptr, nullptr, p_w1h, p_w1l, nullptr, p_part,
            /*lda=*/D, /*ldb=*/KP1, /*ldc=*/H, /*Nvalid=*/H, /*Dvalid=*/D,
            /*itersPerSplit=*/(KP1 / 32) / SPLITS,
            /*splitStride=*/(long long)B * H);
    }
    h1_epilogue_kernel<<<(B * H + 255) / 256, 256>>>(enc_b1, B * H, H);

    // --- z_e, clustering, decoder hiddens ---
    zenc_kernel<<<(B * Z + 255) / 256, 256>>>(enc_w2, enc_b2, o_ze, B, H, Z);
    cluster_kernel<<<(B + 31) / 32, 32>>>(o_ze, emb, o_zq, o_k, o_zd, o_dp, B, Z, K);
    {
        dim3 grid(B, 2);
        dec_h_kernel<<<grid, H>>>(o_ze, o_zq, de_w1, de_b1, dq_w1, dq_b1, B, Z, H);
    }

    // --- decoder output GEMMs: hd[B,H] @ w2t[NP2,H]^T + bias ---
    {
        dim3 grid(NT2, B / 128, 1);
        mma_gemm_kernel<false><<<grid, 256, SMEM_TOTAL>>>(
            nullptr, p_hdh, p_hdl, p_w2eh, p_w2el, de_b2, o_xe,
            /*lda=*/H, /*ldb=*/H, /*ldc=*/D, /*Nvalid=*/D, /*Dvalid=*/D,
            /*itersPerSplit=*/H / 32, /*splitStride=*/0);
        mma_gemm_kernel<false><<<grid, 256, SMEM_TOTAL>>>(
            nullptr, p_hdh + (long long)B * H, p_hdl + (long long)B * H,
            p_w2qh, p_w2ql, dq_b2, o_xq,
            /*lda=*/H, /*ldb=*/H, /*ldc=*/D, /*Nvalid=*/D, /*Dvalid=*/D,
            /*itersPerSplit=*/H / 32, /*splitStride=*/0);
    }
}

// round 5
// speedup vs baseline: 3.9553x; 1.1316x over previous
#include <cuda_runtime.h>
#include <cuda_bf16.h>
#include <cstdint>
#include <math.h>

// ============================================================================
// AnnoCluster on GB300 (plain sm_103 target -> mma.sync HMMA path).
// 3-pass split precision GEMMs: C = Ah*Bh + Ah*Bl + Al*Bh
// R5: x_q via 16-row table + gather (kills 2nd decoder GEMM), uneven split-K=9
//     encoder, smem-cached small kernels.
// ============================================================================

#define BMAX 4096
#define HMAX 128
#define KP1MAX 10240
#define NP2MAX 10112
#define NSPLIT_MAX 16

__device__ float g_part[NSPLIT_MAX * BMAX * HMAX];
__device__ float g_h1[BMAX * HMAX];
__device__ float g_hq[64 * HMAX];
__device__ float g_xqtab[64 * 10240];
__device__ __nv_bfloat16 g_w1h[HMAX * KP1MAX];
__device__ __nv_bfloat16 g_w1l[HMAX * KP1MAX];
__device__ __nv_bfloat16 g_w2eh[NP2MAX * HMAX];
__device__ __nv_bfloat16 g_w2el[NP2MAX * HMAX];
__device__ __nv_bfloat16 g_hdh[BMAX * HMAX];
__device__ __nv_bfloat16 g_hdl[BMAX * HMAX];

// ============================================================================
// helpers
// ============================================================================
__device__ __forceinline__ uint32_t smem_u32(const void* p) {
    uint32_t a;
    asm("{ .reg .u64 t; cvta.to.shared.u64 t, %1; cvt.u32.u64 %0, t; }"
        : "=r"(a) : "l"(p));
    return a;
}
__device__ __forceinline__ void cp16(uint32_t dst, const void* src) {
    asm volatile("cp.async.cg.shared.global [%0], [%1], 16;"
                 :: "r"(dst), "l"(__cvta_generic_to_global(src)) : "memory");
}
#define CP_COMMIT() asm volatile("cp.async.commit_group;" ::: "memory")
#define CP_WAIT(n)  asm volatile("cp.async.wait_group %0;" :: "n"(n) : "memory")

#define LDMX4(r0, r1, r2, r3, a) \
    asm volatile("ldmatrix.sync.aligned.m8n8.x4.shared.b16 {%0,%1,%2,%3}, [%4];" \
                 : "=r"(r0), "=r"(r1), "=r"(r2), "=r"(r3) : "r"(a))

#define MMA_BF16(d, a, b) \
    asm volatile("mma.sync.aligned.m16n8k16.row.col.f32.bf16.bf16.f32 " \
                 "{%0,%1,%2,%3}, {%4,%5,%6,%7}, {%8,%9}, {%0,%1,%2,%3};" \
                 : "+f"((d)[0]), "+f"((d)[1]), "+f"((d)[2]), "+f"((d)[3]) \
                 : "r"((a)[0]), "r"((a)[1]), "r"((a)[2]), "r"((a)[3]), \
                   "r"((b)[0]), "r"((b)[1]))

__device__ __forceinline__ void sts128(uint32_t a, uint32_t x, uint32_t y,
                                       uint32_t z, uint32_t w) {
    asm volatile("st.shared.v4.b32 [%0], {%1, %2, %3, %4};"
                 :: "r"(a), "r"(x), "r"(y), "r"(z), "r"(w) : "memory");
}

__device__ __forceinline__ uint32_t pack_bf16(__nv_bfloat16 a, __nv_bfloat16 b) {
    return ((uint32_t)__bfloat16_as_ushort(b) << 16) | (uint32_t)__bfloat16_as_ushort(a);
}

// tile: 128 rows x 32 bf16 (64B data + 16B pad)
#define TROW 80
#define TILE_BYTES (128 * TROW)
#define STAGE_BYTES (4 * TILE_BYTES)
#define SMEM_TOTAL (2 * STAGE_BYTES)   // 81920 -> 2 CTA/SM

// ============================================================================
// mma.sync 3-pass split GEMM (128x128 C tile, 8 warps of 64x32)
//   CONVA: A fp32, conversion fused. blockIdx.z = split-K slice (uneven OK).
// ============================================================================
template <bool CONVA>
__global__ __launch_bounds__(256, 2)
void mma_gemm_kernel(const float* __restrict__ Afp,
                     const __nv_bfloat16* __restrict__ Ah,
                     const __nv_bfloat16* __restrict__ Al,
                     const __nv_bfloat16* __restrict__ Bh,
                     const __nv_bfloat16* __restrict__ Bl,
                     const float* __restrict__ bias,
                     float* __restrict__ C,
                     int lda, int ldb, int ldc, int Nvalid, int Dvalid,
                     int itersPerSplit, int totalIters, long long splitStride)
{
    extern __shared__ char smem[];
    const uint32_t sb = smem_u32(smem);
    const int tid = threadIdx.x;
    const int wid = tid >> 5;
    const int lid = tid & 31;
    const int mBase = blockIdx.y * 128;
    const int nBase = blockIdx.x * 128;
    C += (long long)blockIdx.z * splitStride;
    const int c0 = blockIdx.z * itersPerSplit;
    const int iters = min(itersPerSplit, totalIters - c0);

    auto load_stage_async = [&](int s, int it) {
        const uint32_t dst = sb + (uint32_t)s * STAGE_BYTES;
        const int k0 = (c0 + it) * 32;
#pragma unroll
        for (int t = 0; t < 2; t++) {
            const int id = t * 256 + tid;
            const int r = id >> 2, c = id & 3;
            const uint32_t o = (uint32_t)r * TROW + (uint32_t)c * 16;
            const size_t boff = (size_t)(nBase + r) * ldb + k0 + c * 8;
            cp16(dst + 2 * TILE_BYTES + o, Bh + boff);
            cp16(dst + 3 * TILE_BYTES + o, Bl + boff);
            if (!CONVA) {
                const size_t aoff = (size_t)(mBase + r) * lda + k0 + c * 8;
                cp16(dst + o,              Ah + aoff);
                cp16(dst + TILE_BYTES + o, Al + aoff);
            }
        }
    };

    const int ar_ = tid >> 1;
    const int ah_ = tid & 1;
    float4 pre[4];
    auto ldg_a = [&](int it) {
        const int k0 = (c0 + it) * 32 + ah_ * 16;
        const float* base = Afp + (size_t)(mBase + ar_) * lda;
#pragma unroll
        for (int q = 0; q < 4; q++) {
            const int gk = k0 + q * 4;
            if (gk + 4 <= Dvalid) {
                pre[q] = *(const float4*)(base + gk);
            } else {
                float4 v = make_float4(0.f, 0.f, 0.f, 0.f);
                if (gk < Dvalid) {
                    v.x = base[gk];
                    if (gk + 1 < Dvalid) v.y = base[gk + 1];
                    if (gk + 2 < Dvalid) v.z = base[gk + 2];
                }
                pre[q] = v;
            }
        }
    };
    auto sts_a = [&](int s) {
        const uint32_t dst = sb + (uint32_t)s * STAGE_BYTES +
                             (uint32_t)ar_ * TROW + (uint32_t)ah_ * 32;
        uint32_t hi[4], lo[4];
#pragma unroll
        for (int q = 0; q < 4; q++) {
            const float fx = pre[q].x, fy = pre[q].y, fz = pre[q].z, fw = pre[q].w;
            __nv_bfloat16 h0 = __float2bfloat16(fx), h1 = __float2bfloat16(fy);
            __nv_bfloat16 h2 = __float2bfloat16(fz), h3 = __float2bfloat16(fw);
            hi[q] = pack_bf16(h0, h1);
            __nv_bfloat16 l0 = __float2bfloat16(fx - __bfloat162float(h0));
            __nv_bfloat16 l1 = __float2bfloat16(fy - __bfloat162float(h1));
            lo[q] = pack_bf16(l0, l1);
            __nv_bfloat16 l2 = __float2bfloat16(fz - __bfloat162float(h2));
            __nv_bfloat16 l3 = __float2bfloat16(fw - __bfloat162float(h3));
            pre[q].x = __uint_as_float(pack_bf16(h2, h3));
            pre[q].y = __uint_as_float(pack_bf16(l2, l3));
        }
        sts128(dst,       hi[0], __float_as_uint(pre[0].x), hi[1], __float_as_uint(pre[1].x));
        sts128(dst + 16,  hi[2], __float_as_uint(pre[2].x), hi[3], __float_as_uint(pre[3].x));
        sts128(dst + TILE_BYTES,      lo[0], __float_as_uint(pre[0].y), lo[1], __float_as_uint(pre[1].y));
        sts128(dst + TILE_BYTES + 16, lo[2], __float_as_uint(pre[2].y), lo[3], __float_as_uint(pre[3].y));
    };

    float acc[4][4][4];
#pragma unroll
    for (int i = 0; i < 4; i++)
#pragma unroll
        for (int j = 0; j < 4; j++)
#pragma unroll
            for (int q = 0; q < 4; q++) acc[i][j][q] = 0.f;

    const int wm = (wid >> 2) * 64;
    const int wn = (wid & 3) * 32;
    const int lr = lid >> 2;
    const int lc = lid & 3;

    const int a_row = lid & 15;
    const int a_kh  = (lid >> 4) * 16;
    const int b_grp = lid >> 3;
    const int b_row = lid & 7;
    const int b_nof = (b_grp >> 1) * 8;
    const int b_kh  = (b_grp & 1) * 16;

    load_stage_async(0, 0);
    CP_COMMIT();
    if (CONVA) ldg_a(0);

    for (int i = 0; i < iters; i++) {
        const int buf = i & 1;
        if (CONVA) sts_a(buf);
        if (i + 1 < iters) { load_stage_async(buf ^ 1, i + 1); CP_COMMIT(); }
        if (i + 1 < iters) { CP_WAIT(1); } else { CP_WAIT(0); }
        __syncthreads();
        if (CONVA && i + 1 < iters) ldg_a(i + 1);

        const uint32_t base = sb + (uint32_t)buf * STAGE_BYTES;
#pragma unroll
        for (int ks = 0; ks < 2; ks++) {
            const uint32_t ko = (uint32_t)ks * 32;
            uint32_t bh[2][4], bl[2][4];
#pragma unroll
            for (int n2 = 0; n2 < 2; n2++) {
                const uint32_t baddr = base + 2 * TILE_BYTES +
                    (uint32_t)(wn + n2 * 16 + b_nof + b_row) * TROW + ko + b_kh;
                LDMX4(bh[n2][0], bh[n2][1], bh[n2][2], bh[n2][3], baddr);
                LDMX4(bl[n2][0], bl[n2][1], bl[n2][2], bl[n2][3], baddr + TILE_BYTES);
            }
#pragma unroll
            for (int mi = 0; mi < 4; mi++) {
                const uint32_t aaddr = base +
                    (uint32_t)(wm + mi * 16 + a_row) * TROW + ko + a_kh;
                uint32_t a[4], al4[4];
                LDMX4(a[0], a[1], a[2], a[3], aaddr);
                LDMX4(al4[0], al4[1], al4[2], al4[3], aaddr + TILE_BYTES);
#pragma unroll
                for (int n2 = 0; n2 < 2; n2++) {
#pragma unroll
                    for (int w = 0; w < 2; w++) {
                        float* d = acc[mi][n2 * 2 + w];
                        MMA_BF16(d, a,   (bh[n2] + w * 2));
                        MMA_BF16(d, a,   (bl[n2] + w * 2));
                        MMA_BF16(d, al4, (bh[n2] + w * 2));
                    }
                }
            }
        }
        __syncthreads();
    }
    CP_WAIT(0);

    // epilogue via smem stage -> coalesced stores
    float* stage = (float*)smem;
#pragma unroll
    for (int mi = 0; mi < 4; mi++) {
        const int r0 = wm + mi * 16 + lr;
#pragma unroll
        for (int ni = 0; ni < 4; ni++) {
            const int c = wn + ni * 8 + lc * 2;
            stage[r0 * 129 + c]           = acc[mi][ni][0];
            stage[r0 * 129 + c + 1]       = acc[mi][ni][1];
            stage[(r0 + 8) * 129 + c]     = acc[mi][ni][2];
            stage[(r0 + 8) * 129 + c + 1] = acc[mi][ni][3];
        }
    }
    __syncthreads();
#pragma unroll 4
    for (int idx = tid; idx < 128 * 128; idx += 256) {
        const int r = idx >> 7, c = idx & 127;
        const int n = nBase + c;
        if (n < Nvalid) {
            float v = stage[r * 129 + c];
            if (bias) v += bias[n];
            C[(long long)(mBase + r) * ldc + n] = v;
        }
    }
}

// ============================================================================
// transpose + bf16 hi/lo split: in[K,N] fp32 -> oh/ol [Npad, Kpad]
// ============================================================================
__global__ void transpose_split_kernel(const float* __restrict__ in,
                                       __nv_bfloat16* __restrict__ oh,
                                       __nv_bfloat16* __restrict__ ol,
                                       int K, int N, int Kpad, int Npad)
{
    __shared__ float t[32][33];
    const int k0 = blockIdx.x * 32, n0 = blockIdx.y * 32;
    for (int i = threadIdx.y; i < 32; i += 8) {
        int k = k0 + i, n = n0 + threadIdx.x;
        t[i][threadIdx.x] = (k < K && n < N) ? in[(size_t)k * N + n] : 0.f;
    }
    __syncthreads();
    for (int i = threadIdx.y; i < 32; i += 8) {
        int n = n0 + i, k = k0 + threadIdx.x;
        if (n < Npad && k < Kpad) {
            float v = t[threadIdx.x][i];
            __nv_bfloat16 h = __float2bfloat16(v);
            oh[(size_t)n * Kpad + k] = h;
            ol[(size_t)n * Kpad + k] = __float2bfloat16(v - __bfloat162float(h));
        }
    }
}

// ============================================================================
// small kernels
// ============================================================================
__global__ void h1_epilogue_kernel(const float* __restrict__ bias, int MH, int H,
                                   int nsplits)
{
    int i = blockIdx.x * blockDim.x + threadIdx.x;
    if (i >= MH) return;
    float s = 0.f;
    for (int p = 0; p < nsplits; p++) s += g_part[(long long)p * MH + i];
    s += bias[i % H];
    g_h1[i] = fmaxf(s, 0.f);
}

// z_e: block handles 256/Z rows; w2 cached in smem
__global__ void zenc_kernel(const float* __restrict__ w2, const float* __restrict__ b2,
                            float* __restrict__ ze, int B, int H, int Z)
{
    __shared__ float w2s[HMAX * 64];
    const int tid = threadIdx.x;
    for (int i = tid; i < H * Z; i += 256) w2s[i] = w2[i];
    __syncthreads();
    const int rows = 256 / Z;
    const int b = blockIdx.x * rows + tid / Z;
    const int z = tid % Z;
    if (b >= B) return;
    const float* h1 = g_h1 + (size_t)b * H;
    float acc = b2[z];
    for (int k = 0; k < H; k++) acc = fmaf(h1[k], w2s[k * Z + z], acc);
    ze[(size_t)b * Z + z] = acc;
}

#define MAXZ 64
#define MAXKC 64
__global__ void cluster_kernel(const float* __restrict__ ze, const float* __restrict__ emb,
                               float* __restrict__ zq, float* __restrict__ kout,
                               float* __restrict__ zd, float* __restrict__ dp,
                               int B, int Z, int K)
{
    int b = blockIdx.x * blockDim.x + threadIdx.x;
    if (b >= B) return;

    float zrow[MAXZ];
    for (int z = 0; z < Z; z++) zrow[z] = ze[(long long)b * Z + z];

    float p[MAXKC];
    float sum = 0.f;
    for (int k = 0; k < K; k++) {
        float d = 0.f;
        for (int z = 0; z < Z; z++) {
            float t = zrow[z] - emb[k * Z + z];
            d = fmaf(t, t, d);
        }
        zd[(long long)b * K + k] = d;
        float pk = __powf(1.0f + d * 0.1f, -5.5f);
        p[k] = pk;
        sum += pk;
    }
    float inv = 1.0f / sum;
    int best = 0;
    float bestv = -1.f;
    for (int k = 0; k < K; k++) {
        float v = p[k] * inv;
        dp[(long long)b * K + k] = v;
        if (v > bestv) { bestv = v; best = k; }
    }
    kout[b] = (float)best;
    for (int z = 0; z < Z; z++) zq[(long long)b * Z + z] = emb[best * Z + z];
}

// e-decoder hidden: 16 rows per block, w1 in smem; writes bf16 hi/lo
__global__ void dec_h_e_kernel(const float* __restrict__ ze,
                               const float* __restrict__ w1,
                               const float* __restrict__ b1,
                               int B, int Z, int H)
{
    __shared__ float w1s[MAXZ * HMAX];
    __shared__ float zs[16 * MAXZ];
    const int tid = threadIdx.x;   // 128
    const int b0 = blockIdx.x * 16;
    for (int i = tid; i < Z * H; i += 128) w1s[i] = w1[i];
    for (int i = tid; i < 16 * Z; i += 128) zs[i] = ze[(size_t)b0 * Z + i];
    __syncthreads();
    const int h = tid;
    if (h >= H) return;
    const float bb = b1[h];
    for (int r = 0; r < 16; r++) {
        float acc = bb;
        for (int k = 0; k < Z; k++) acc = fmaf(zs[r * Z + k], w1s[k * H + h], acc);
        float v = fmaxf(acc, 0.f);
        const size_t idx = (size_t)(b0 + r) * H + h;
        __nv_bfloat16 hi = __float2bfloat16(v);
        g_hdh[idx] = hi;
        g_hdl[idx] = __float2bfloat16(v - __bfloat162float(hi));
    }
}

// q-decoder hidden table: hq[K,H] = relu(emb @ w1 + b1), single block
__global__ void hq_kernel(const float* __restrict__ emb,
                          const float* __restrict__ w1,
                          const float* __restrict__ b1,
                          int K, int Z, int H)
{
    __shared__ float es[64 * MAXZ];
    const int tid = threadIdx.x;   // 128
    for (int i = tid; i < K * Z; i += 128) es[i] = emb[i];
    __syncthreads();
    if (tid >= H) return;
    for (int r = 0; r < K; r++) {
        float acc = b1[tid];
        for (int k = 0; k < Z; k++) acc = fmaf(es[r * Z + k], w1[k * H + tid], acc);
        g_hq[r * HMAX + tid] = fmaxf(acc, 0.f);
    }
}

// xq table: tab[K,D] = hq @ w2 + b2  (w2 read exactly once)
__global__ void xqtab_kernel(const float* __restrict__ w2,
                             const float* __restrict__ b2,
                             int K, int H, int D)
{
    __shared__ float hs[16 * HMAX];
    const int tid = threadIdx.x;   // 256
    for (int i = tid; i < K * H; i += 256) hs[(i / H) * HMAX + (i % H)] = g_hq[(i / H) * HMAX + (i % H)];
    __syncthreads();
    const int c = blockIdx.x * 256 + tid;
    if (c >= D) return;
    float acc[16];
    const float bb = b2[c];
#pragma unroll
    for (int r = 0; r < 16; r++) acc[r] = bb;
    for (int k = 0; k < H; k++) {
        const float wv = w2[(size_t)k * D + c];
#pragma unroll
        for (int r = 0; r < 16; r++) acc[r] = fmaf(hs[r * HMAX + k], wv, acc[r]);
    }
#pragma unroll
    for (int r = 0; r < 16; r++)
        if (r < K) g_xqtab[(size_t)r * D + c] = acc[r];
}

// x_q gather: x_q[b,:] = tab[k[b],:]  (float4)
__global__ void gather_xq_kernel(const float* __restrict__ kf,
                                 float* __restrict__ xq, int B, int D)
{
    const int perRow = D >> 2;
    const int idx = blockIdx.x * blockDim.x + threadIdx.x;
    if (idx >= B * perRow) return;
    const int b = idx / perRow;
    const int c = idx - b * perRow;
    const int kb = (int)kf[b];
    const float4 v = ((const float4*)(g_xqtab + (size_t)kb * D))[c];
    ((float4*)(xq + (size_t)b * D))[c] = v;
}

// ============================================================================
extern "C" void kernel_launch(void* const* d_in, const int* in_sizes, int n_in,
                              void* d_out, int out_size)
{
    const float* x      = (const float*)d_in[0];
    const float* enc_w1 = (const float*)d_in[1];
    const float* enc_b1 = (const float*)d_in[2];
    const float* enc_w2 = (const float*)d_in[3];
    const float* enc_b2 = (const float*)d_in[4];
    const float* emb    = (const float*)d_in[5];
    const float* de_w1  = (const float*)d_in[6];
    const float* de_b1  = (const float*)d_in[7];
    const float* de_w2  = (const float*)d_in[8];
    const float* de_b2  = (const float*)d_in[9];
    const float* dq_w1  = (const float*)d_in[10];
    const float* dq_b1  = (const float*)d_in[11];
    const float* dq_w2  = (const float*)d_in[12];
    const float* dq_b2  = (const float*)d_in[13];

    const int H = in_sizes[2];
    const int Z = in_sizes[4];
    const int D = in_sizes[1] / H;
    const int B = in_sizes[0] / D;
    const int K = in_sizes[5] / Z;

    const int KP1 = ((D + 255) / 256) * 256;    // 10240
    const int NT2 = (D + 127) / 128;            // 79
    const int NP2 = NT2 * 128;                  // 10112
    const int totalIters = KP1 / 32;            // 320
    const int NSPLIT = 9;
    const int iPS = (totalIters + NSPLIT - 1) / NSPLIT;   // 36

    float* out = (float*)d_out;
    const long long BD = (long long)B * D;
    const long long BZ = (long long)B * Z;
    float* o_xe = out;
    float* o_xq = out + BD;
    float* o_ze = out + 2 * BD;
    float* o_zq = out + 2 * BD + BZ;
    float* o_k  = out + 2 * BD + 2 * BZ;
    float* o_zd = o_k + B;
    float* o_dp = o_zd + (long long)B * K;
    (void)out_size; (void)n_in;

    float* p_part;
    __nv_bfloat16 *p_w1h, *p_w1l, *p_w2eh, *p_w2el, *p_hdh, *p_hdl;
    cudaGetSymbolAddress((void**)&p_part, g_part);
    cudaGetSymbolAddress((void**)&p_w1h, g_w1h);
    cudaGetSymbolAddress((void**)&p_w1l, g_w1l);
    cudaGetSymbolAddress((void**)&p_w2eh, g_w2eh);
    cudaGetSymbolAddress((void**)&p_w2el, g_w2el);
    cudaGetSymbolAddress((void**)&p_hdh, g_hdh);
    cudaGetSymbolAddress((void**)&p_hdl, g_hdl);

    cudaFuncSetAttribute(mma_gemm_kernel<true>,
                         cudaFuncAttributeMaxDynamicSharedMemorySize, SMEM_TOTAL);
    cudaFuncSetAttribute(mma_gemm_kernel<false>,
                         cudaFuncAttributeMaxDynamicSharedMemorySize, SMEM_TOTAL);

    // --- weight prep ---
    {
        dim3 blk(32, 8);
        dim3 g1((KP1 + 31) / 32, (H + 31) / 32);
        transpose_split_kernel<<<g1, blk>>>(enc_w1, p_w1h, p_w1l, D, H, KP1, H);
        dim3 g2((H + 31) / 32, (NP2 + 31) / 32);
        transpose_split_kernel<<<g2, blk>>>(de_w2, p_w2eh, p_w2el, H, D, H, NP2);
    }

    // --- q-decoder table (only K=16 distinct rows) ---
    hq_kernel<<<1, 128>>>(emb, dq_w1, dq_b1, K, Z, H);
    xqtab_kernel<<<(D + 255) / 256, 256>>>(dq_w2, dq_b2, K, H, D);

    // --- encoder GEMM1: fused fp32->split, uneven split-K=9 ---
    {
        dim3 grid(1, B / 128, NSPLIT);
        mma_gemm_kernel<true><<<grid, 256, SMEM_TOTAL>>>(
            x, nullptr, nullptr, p_w1h, p_w1l, nullptr, p_part,
            /*lda=*/D, /*ldb=*/KP1, /*ldc=*/H, /*Nvalid=*/H, /*Dvalid=*/D,
            iPS, totalIters, /*splitStride=*/(long long)B * H);
    }
    h1_epilogue_kernel<<<(B * H + 255) / 256, 256>>>(enc_b1, B * H, H, NSPLIT);

    // --- z_e, clustering, e-decoder hidden ---
    zenc_kernel<<<B / (256 / Z), 256>>>(enc_w2, enc_b2, o_ze, B, H, Z);
    cluster_kernel<<<(B + 31) / 32, 32>>>(o_ze, emb, o_zq, o_k, o_zd, o_dp, B, Z, K);
    dec_h_e_kernel<<<B / 16, 128>>>(o_ze, de_w1, de_b1, B, Z, H);

    // --- x_q: gather from table ---
    {
        const int n = B * (D / 4);
        gather_xq_kernel<<<(n + 255) / 256, 256>>>(o_k, o_xq, B, D);
    }

    // --- e-decoder output GEMM ---
    {
        dim3 grid(NT2, B / 128, 1);
        mma_gemm_kernel<false><<<grid, 256, SMEM_TOTAL>>>(
            nullptr, p_hdh, p_hdl, p_w2eh, p_w2el, de_b2, o_xe,
            /*lda=*/H, /*ldb=*/H, /*ldc=*/D, /*Nvalid=*/D, /*Dvalid=*/D,
            /*itersPerSplit=*/H / 32, /*totalIters=*/H / 32, /*splitStride=*/0);
    }
}

// round 6
// speedup vs baseline: 4.3260x; 1.0937x over previous
#include <cuda_runtime.h>
#include <cuda_bf16.h>
#include <cstdint>
#include <math.h>

// ============================================================================
// AnnoCluster on GB300 (plain sm_103 target -> mma.sync HMMA path).
// 3-pass split precision GEMMs: C = Ah*Bh + Ah*Bl + Al*Bh
// R6: parallel split-K xq-table (41us -> ~7us), vectorized w1 transpose.
// ============================================================================

#define BMAX 4096
#define HMAX 128
#define KP1MAX 10240
#define NP2MAX 10112
#define NSPLIT_MAX 16

__device__ float g_part[NSPLIT_MAX * BMAX * HMAX];   // also reused as xqtab partials
__device__ float g_h1[BMAX * HMAX];
__device__ float g_hq[64 * HMAX];
__device__ float g_xqtab[64 * 10240];
__device__ __nv_bfloat16 g_w1h[HMAX * KP1MAX];
__device__ __nv_bfloat16 g_w1l[HMAX * KP1MAX];
__device__ __nv_bfloat16 g_w2eh[NP2MAX * HMAX];
__device__ __nv_bfloat16 g_w2el[NP2MAX * HMAX];
__device__ __nv_bfloat16 g_hdh[BMAX * HMAX];
__device__ __nv_bfloat16 g_hdl[BMAX * HMAX];

// ============================================================================
// helpers
// ============================================================================
__device__ __forceinline__ uint32_t smem_u32(const void* p) {
    uint32_t a;
    asm("{ .reg .u64 t; cvta.to.shared.u64 t, %1; cvt.u32.u64 %0, t; }"
        : "=r"(a) : "l"(p));
    return a;
}
__device__ __forceinline__ void cp16(uint32_t dst, const void* src) {
    asm volatile("cp.async.cg.shared.global [%0], [%1], 16;"
                 :: "r"(dst), "l"(__cvta_generic_to_global(src)) : "memory");
}
#define CP_COMMIT() asm volatile("cp.async.commit_group;" ::: "memory")
#define CP_WAIT(n)  asm volatile("cp.async.wait_group %0;" :: "n"(n) : "memory")

#define LDMX4(r0, r1, r2, r3, a) \
    asm volatile("ldmatrix.sync.aligned.m8n8.x4.shared.b16 {%0,%1,%2,%3}, [%4];" \
                 : "=r"(r0), "=r"(r1), "=r"(r2), "=r"(r3) : "r"(a))

#define MMA_BF16(d, a, b) \
    asm volatile("mma.sync.aligned.m16n8k16.row.col.f32.bf16.bf16.f32 " \
                 "{%0,%1,%2,%3}, {%4,%5,%6,%7}, {%8,%9}, {%0,%1,%2,%3};" \
                 : "+f"((d)[0]), "+f"((d)[1]), "+f"((d)[2]), "+f"((d)[3]) \
                 : "r"((a)[0]), "r"((a)[1]), "r"((a)[2]), "r"((a)[3]), \
                   "r"((b)[0]), "r"((b)[1]))

__device__ __forceinline__ void sts128(uint32_t a, uint32_t x, uint32_t y,
                                       uint32_t z, uint32_t w) {
    asm volatile("st.shared.v4.b32 [%0], {%1, %2, %3, %4};"
                 :: "r"(a), "r"(x), "r"(y), "r"(z), "r"(w) : "memory");
}

__device__ __forceinline__ uint32_t pack_bf16(__nv_bfloat16 a, __nv_bfloat16 b) {
    return ((uint32_t)__bfloat16_as_ushort(b) << 16) | (uint32_t)__bfloat16_as_ushort(a);
}

// tile: 128 rows x 32 bf16 (64B data + 16B pad)
#define TROW 80
#define TILE_BYTES (128 * TROW)
#define STAGE_BYTES (4 * TILE_BYTES)
#define SMEM_TOTAL (2 * STAGE_BYTES)   // 81920 -> 2 CTA/SM

// ============================================================================
// mma.sync 3-pass split GEMM (128x128 C tile, 8 warps of 64x32)
// ============================================================================
template <bool CONVA>
__global__ __launch_bounds__(256, 2)
void mma_gemm_kernel(const float* __restrict__ Afp,
                     const __nv_bfloat16* __restrict__ Ah,
                     const __nv_bfloat16* __restrict__ Al,
                     const __nv_bfloat16* __restrict__ Bh,
                     const __nv_bfloat16* __restrict__ Bl,
                     const float* __restrict__ bias,
                     float* __restrict__ C,
                     int lda, int ldb, int ldc, int Nvalid, int Dvalid,
                     int itersPerSplit, int totalIters, long long splitStride)
{
    extern __shared__ char smem[];
    const uint32_t sb = smem_u32(smem);
    const int tid = threadIdx.x;
    const int wid = tid >> 5;
    const int lid = tid & 31;
    const int mBase = blockIdx.y * 128;
    const int nBase = blockIdx.x * 128;
    C += (long long)blockIdx.z * splitStride;
    const int c0 = blockIdx.z * itersPerSplit;
    const int iters = min(itersPerSplit, totalIters - c0);

    auto load_stage_async = [&](int s, int it) {
        const uint32_t dst = sb + (uint32_t)s * STAGE_BYTES;
        const int k0 = (c0 + it) * 32;
#pragma unroll
        for (int t = 0; t < 2; t++) {
            const int id = t * 256 + tid;
            const int r = id >> 2, c = id & 3;
            const uint32_t o = (uint32_t)r * TROW + (uint32_t)c * 16;
            const size_t boff = (size_t)(nBase + r) * ldb + k0 + c * 8;
            cp16(dst + 2 * TILE_BYTES + o, Bh + boff);
            cp16(dst + 3 * TILE_BYTES + o, Bl + boff);
            if (!CONVA) {
                const size_t aoff = (size_t)(mBase + r) * lda + k0 + c * 8;
                cp16(dst + o,              Ah + aoff);
                cp16(dst + TILE_BYTES + o, Al + aoff);
            }
        }
    };

    const int ar_ = tid >> 1;
    const int ah_ = tid & 1;
    float4 pre[4];
    auto ldg_a = [&](int it) {
        const int k0 = (c0 + it) * 32 + ah_ * 16;
        const float* base = Afp + (size_t)(mBase + ar_) * lda;
#pragma unroll
        for (int q = 0; q < 4; q++) {
            const int gk = k0 + q * 4;
            if (gk + 4 <= Dvalid) {
                pre[q] = *(const float4*)(base + gk);
            } else {
                float4 v = make_float4(0.f, 0.f, 0.f, 0.f);
                if (gk < Dvalid) {
                    v.x = base[gk];
                    if (gk + 1 < Dvalid) v.y = base[gk + 1];
                    if (gk + 2 < Dvalid) v.z = base[gk + 2];
                }
                pre[q] = v;
            }
        }
    };
    auto sts_a = [&](int s) {
        const uint32_t dst = sb + (uint32_t)s * STAGE_BYTES +
                             (uint32_t)ar_ * TROW + (uint32_t)ah_ * 32;
        uint32_t hi[4], lo[4];
#pragma unroll
        for (int q = 0; q < 4; q++) {
            const float fx = pre[q].x, fy = pre[q].y, fz = pre[q].z, fw = pre[q].w;
            __nv_bfloat16 h0 = __float2bfloat16(fx), h1 = __float2bfloat16(fy);
            __nv_bfloat16 h2 = __float2bfloat16(fz), h3 = __float2bfloat16(fw);
            hi[q] = pack_bf16(h0, h1);
            __nv_bfloat16 l0 = __float2bfloat16(fx - __bfloat162float(h0));
            __nv_bfloat16 l1 = __float2bfloat16(fy - __bfloat162float(h1));
            lo[q] = pack_bf16(l0, l1);
            __nv_bfloat16 l2 = __float2bfloat16(fz - __bfloat162float(h2));
            __nv_bfloat16 l3 = __float2bfloat16(fw - __bfloat162float(h3));
            pre[q].x = __uint_as_float(pack_bf16(h2, h3));
            pre[q].y = __uint_as_float(pack_bf16(l2, l3));
        }
        sts128(dst,       hi[0], __float_as_uint(pre[0].x), hi[1], __float_as_uint(pre[1].x));
        sts128(dst + 16,  hi[2], __float_as_uint(pre[2].x), hi[3], __float_as_uint(pre[3].x));
        sts128(dst + TILE_BYTES,      lo[0], __float_as_uint(pre[0].y), lo[1], __float_as_uint(pre[1].y));
        sts128(dst + TILE_BYTES + 16, lo[2], __float_as_uint(pre[2].y), lo[3], __float_as_uint(pre[3].y));
    };

    float acc[4][4][4];
#pragma unroll
    for (int i = 0; i < 4; i++)
#pragma unroll
        for (int j = 0; j < 4; j++)
#pragma unroll
            for (int q = 0; q < 4; q++) acc[i][j][q] = 0.f;

    const int wm = (wid >> 2) * 64;
    const int wn = (wid & 3) * 32;
    const int lr = lid >> 2;
    const int lc = lid & 3;

    const int a_row = lid & 15;
    const int a_kh  = (lid >> 4) * 16;
    const int b_grp = lid >> 3;
    const int b_row = lid & 7;
    const int b_nof = (b_grp >> 1) * 8;
    const int b_kh  = (b_grp & 1) * 16;

    load_stage_async(0, 0);
    CP_COMMIT();
    if (CONVA) ldg_a(0);

    for (int i = 0; i < iters; i++) {
        const int buf = i & 1;
        if (CONVA) sts_a(buf);
        if (i + 1 < iters) { load_stage_async(buf ^ 1, i + 1); CP_COMMIT(); }
        if (i + 1 < iters) { CP_WAIT(1); } else { CP_WAIT(0); }
        __syncthreads();
        if (CONVA && i + 1 < iters) ldg_a(i + 1);

        const uint32_t base = sb + (uint32_t)buf * STAGE_BYTES;
#pragma unroll
        for (int ks = 0; ks < 2; ks++) {
            const uint32_t ko = (uint32_t)ks * 32;
            uint32_t bh[2][4], bl[2][4];
#pragma unroll
            for (int n2 = 0; n2 < 2; n2++) {
                const uint32_t baddr = base + 2 * TILE_BYTES +
                    (uint32_t)(wn + n2 * 16 + b_nof + b_row) * TROW + ko + b_kh;
                LDMX4(bh[n2][0], bh[n2][1], bh[n2][2], bh[n2][3], baddr);
                LDMX4(bl[n2][0], bl[n2][1], bl[n2][2], bl[n2][3], baddr + TILE_BYTES);
            }
#pragma unroll
            for (int mi = 0; mi < 4; mi++) {
                const uint32_t aaddr = base +
                    (uint32_t)(wm + mi * 16 + a_row) * TROW + ko + a_kh;
                uint32_t a[4], al4[4];
                LDMX4(a[0], a[1], a[2], a[3], aaddr);
                LDMX4(al4[0], al4[1], al4[2], al4[3], aaddr + TILE_BYTES);
#pragma unroll
                for (int n2 = 0; n2 < 2; n2++) {
#pragma unroll
                    for (int w = 0; w < 2; w++) {
                        float* d = acc[mi][n2 * 2 + w];
                        MMA_BF16(d, a,   (bh[n2] + w * 2));
                        MMA_BF16(d, a,   (bl[n2] + w * 2));
                        MMA_BF16(d, al4, (bh[n2] + w * 2));
                    }
                }
            }
        }
        __syncthreads();
    }
    CP_WAIT(0);

    // epilogue via smem stage -> coalesced stores
    float* stage = (float*)smem;
#pragma unroll
    for (int mi = 0; mi < 4; mi++) {
        const int r0 = wm + mi * 16 + lr;
#pragma unroll
        for (int ni = 0; ni < 4; ni++) {
            const int c = wn + ni * 8 + lc * 2;
            stage[r0 * 129 + c]           = acc[mi][ni][0];
            stage[r0 * 129 + c + 1]       = acc[mi][ni][1];
            stage[(r0 + 8) * 129 + c]     = acc[mi][ni][2];
            stage[(r0 + 8) * 129 + c + 1] = acc[mi][ni][3];
        }
    }
    __syncthreads();
#pragma unroll 4
    for (int idx = tid; idx < 128 * 128; idx += 256) {
        const int r = idx >> 7, c = idx & 127;
        const int n = nBase + c;
        if (n < Nvalid) {
            float v = stage[r * 129 + c];
            if (bias) v += bias[n];
            C[(long long)(mBase + r) * ldc + n] = v;
        }
    }
}

// ============================================================================
// transpose + bf16 hi/lo split: in[K,N] fp32 -> oh/ol [Npad, Kpad]
// ============================================================================
__global__ void transpose_split_kernel(const float* __restrict__ in,
                                       __nv_bfloat16* __restrict__ oh,
                                       __nv_bfloat16* __restrict__ ol,
                                       int K, int N, int Kpad, int Npad)
{
    __shared__ float t[32][33];
    const int k0 = blockIdx.x * 32, n0 = blockIdx.y * 32;
    for (int i = threadIdx.y; i < 32; i += 8) {
        int k = k0 + i, n = n0 + threadIdx.x;
        t[i][threadIdx.x] = (k < K && n < N) ? in[(size_t)k * N + n] : 0.f;
    }
    __syncthreads();
    for (int i = threadIdx.y; i < 32; i += 8) {
        int n = n0 + i, k = k0 + threadIdx.x;
        if (n < Npad && k < Kpad) {
            float v = t[threadIdx.x][i];
            __nv_bfloat16 h = __float2bfloat16(v);
            oh[(size_t)n * Kpad + k] = h;
            ol[(size_t)n * Kpad + k] = __float2bfloat16(v - __bfloat162float(h));
        }
    }
}

// ============================================================================
// small kernels
// ============================================================================
__global__ void h1_epilogue_kernel(const float* __restrict__ bias, int MH, int H,
                                   int nsplits)
{
    int i = blockIdx.x * blockDim.x + threadIdx.x;
    if (i >= MH) return;
    float s = 0.f;
    for (int p = 0; p < nsplits; p++) s += g_part[(long long)p * MH + i];
    s += bias[i % H];
    g_h1[i] = fmaxf(s, 0.f);
}

// z_e: block handles 256/Z rows; w2 cached in smem
__global__ void zenc_kernel(const float* __restrict__ w2, const float* __restrict__ b2,
                            float* __restrict__ ze, int B, int H, int Z)
{
    __shared__ float w2s[HMAX * 64];
    const int tid = threadIdx.x;
    for (int i = tid; i < H * Z; i += 256) w2s[i] = w2[i];
    __syncthreads();
    const int rows = 256 / Z;
    const int b = blockIdx.x * rows + tid / Z;
    const int z = tid % Z;
    if (b >= B) return;
    const float* h1 = g_h1 + (size_t)b * H;
    float acc = b2[z];
    for (int k = 0; k < H; k++) acc = fmaf(h1[k], w2s[k * Z + z], acc);
    ze[(size_t)b * Z + z] = acc;
}

#define MAXZ 64
#define MAXKC 64
__global__ void cluster_kernel(const float* __restrict__ ze, const float* __restrict__ emb,
                               float* __restrict__ zq, float* __restrict__ kout,
                               float* __restrict__ zd, float* __restrict__ dp,
                               int B, int Z, int K)
{
    int b = blockIdx.x * blockDim.x + threadIdx.x;
    if (b >= B) return;

    float zrow[MAXZ];
    for (int z = 0; z < Z; z++) zrow[z] = ze[(long long)b * Z + z];

    float p[MAXKC];
    float sum = 0.f;
    for (int k = 0; k < K; k++) {
        float d = 0.f;
        for (int z = 0; z < Z; z++) {
            float t = zrow[z] - emb[k * Z + z];
            d = fmaf(t, t, d);
        }
        zd[(long long)b * K + k] = d;
        float pk = __powf(1.0f + d * 0.1f, -5.5f);
        p[k] = pk;
        sum += pk;
    }
    float inv = 1.0f / sum;
    int best = 0;
    float bestv = -1.f;
    for (int k = 0; k < K; k++) {
        float v = p[k] * inv;
        dp[(long long)b * K + k] = v;
        if (v > bestv) { bestv = v; best = k; }
    }
    kout[b] = (float)best;
    for (int z = 0; z < Z; z++) zq[(long long)b * Z + z] = emb[best * Z + z];
}

// e-decoder hidden: 16 rows per block, w1 in smem; writes bf16 hi/lo
__global__ void dec_h_e_kernel(const float* __restrict__ ze,
                               const float* __restrict__ w1,
                               const float* __restrict__ b1,
                               int B, int Z, int H)
{
    __shared__ float w1s[MAXZ * HMAX];
    __shared__ float zs[16 * MAXZ];
    const int tid = threadIdx.x;   // 128
    const int b0 = blockIdx.x * 16;
    for (int i = tid; i < Z * H; i += 128) w1s[i] = w1[i];
    for (int i = tid; i < 16 * Z; i += 128) zs[i] = ze[(size_t)b0 * Z + i];
    __syncthreads();
    const int h = tid;
    if (h >= H) return;
    const float bb = b1[h];
    for (int r = 0; r < 16; r++) {
        float acc = bb;
        for (int k = 0; k < Z; k++) acc = fmaf(zs[r * Z + k], w1s[k * H + h], acc);
        float v = fmaxf(acc, 0.f);
        const size_t idx = (size_t)(b0 + r) * H + h;
        __nv_bfloat16 hi = __float2bfloat16(v);
        g_hdh[idx] = hi;
        g_hdl[idx] = __float2bfloat16(v - __bfloat162float(hi));
    }
}

// q-decoder hidden table: hq[K,H] = relu(emb @ w1 + b1), single block
__global__ void hq_kernel(const float* __restrict__ emb,
                          const float* __restrict__ w1,
                          const float* __restrict__ b1,
                          int K, int Z, int H)
{
    __shared__ float es[64 * MAXZ];
    const int tid = threadIdx.x;   // 128
    for (int i = tid; i < K * Z; i += 128) es[i] = emb[i];
    __syncthreads();
    if (tid >= H) return;
    for (int r = 0; r < K; r++) {
        float acc = b1[tid];
        for (int k = 0; k < Z; k++) acc = fmaf(es[r * Z + k], w1[k * H + tid], acc);
        g_hq[r * HMAX + tid] = fmaxf(acc, 0.f);
    }
}

// ---- xq table, split-K partials: part[ks][r][D] += hq[r, krange] * w2 ----
// grid (ceil(D/256), 8), block 256. Partials land in g_part (free until
// the encoder GEMM runs later in the stream).
#define XQ_KSPLIT 8
__global__ void xqtab_part_kernel(const float* __restrict__ w2,
                                  int K, int H, int D)
{
    __shared__ float hs[16 * 16];          // 16 rows x 16 k-slice
    const int tid = threadIdx.x;
    const int ks = blockIdx.y;
    const int kw = H / XQ_KSPLIT;          // 16
    const int kbase = ks * kw;
    if (tid < K * kw) {
        const int r = tid / kw, kk = tid % kw;
        hs[r * 16 + kk] = g_hq[r * HMAX + kbase + kk];
    }
    __syncthreads();
    const int c = blockIdx.x * 256 + tid;
    if (c >= D) return;
    float acc[16];
#pragma unroll
    for (int r = 0; r < 16; r++) acc[r] = 0.f;
#pragma unroll
    for (int kk = 0; kk < 16; kk++) {
        const float wv = w2[(size_t)(kbase + kk) * D + c];
#pragma unroll
        for (int r = 0; r < 16; r++) acc[r] = fmaf(hs[r * 16 + kk], wv, acc[r]);
    }
    float* part = g_part + (size_t)ks * 16 * D;
#pragma unroll
    for (int r = 0; r < 16; r++)
        if (r < K) part[(size_t)r * D + c] = acc[r];
}

// reduce partials + bias -> g_xqtab[r, c]
__global__ void xqtab_reduce_kernel(const float* __restrict__ b2, int K, int D)
{
    const int idx = blockIdx.x * blockDim.x + threadIdx.x;
    if (idx >= K * D) return;
    const int r = idx / D;
    const int c = idx - r * D;
    float s = b2[c];
#pragma unroll
    for (int ks = 0; ks < XQ_KSPLIT; ks++)
        s += g_part[(size_t)ks * 16 * D + (size_t)r * D + c];
    g_xqtab[(size_t)r * D + c] = s;
}

// x_q gather: x_q[b,:] = tab[k[b],:]  (float4)
__global__ void gather_xq_kernel(const float* __restrict__ kf,
                                 float* __restrict__ xq, int B, int D)
{
    const int perRow = D >> 2;
    const int idx = blockIdx.x * blockDim.x + threadIdx.x;
    if (idx >= B * perRow) return;
    const int b = idx / perRow;
    const int c = idx - b * perRow;
    const int kb = (int)kf[b];
    const float4 v = ((const float4*)(g_xqtab + (size_t)kb * D))[c];
    ((float4*)(xq + (size_t)b * D))[c] = v;
}

// ============================================================================
extern "C" void kernel_launch(void* const* d_in, const int* in_sizes, int n_in,
                              void* d_out, int out_size)
{
    const float* x      = (const float*)d_in[0];
    const float* enc_w1 = (const float*)d_in[1];
    const float* enc_b1 = (const float*)d_in[2];
    const float* enc_w2 = (const float*)d_in[3];
    const float* enc_b2 = (const float*)d_in[4];
    const float* emb    = (const float*)d_in[5];
    const float* de_w1  = (const float*)d_in[6];
    const float* de_b1  = (const float*)d_in[7];
    const float* de_w2  = (const float*)d_in[8];
    const float* de_b2  = (const float*)d_in[9];
    const float* dq_w1  = (const float*)d_in[10];
    const float* dq_b1  = (const float*)d_in[11];
    const float* dq_w2  = (const float*)d_in[12];
    const float* dq_b2  = (const float*)d_in[13];

    const int H = in_sizes[2];
    const int Z = in_sizes[4];
    const int D = in_sizes[1] / H;
    const int B = in_sizes[0] / D;
    const int K = in_sizes[5] / Z;

    const int KP1 = ((D + 255) / 256) * 256;    // 10240
    const int NT2 = (D + 127) / 128;            // 79
    const int NP2 = NT2 * 128;                  // 10112
    const int totalIters = KP1 / 32;            // 320
    const int NSPLIT = 9;
    const int iPS = (totalIters + NSPLIT - 1) / NSPLIT;   // 36

    float* out = (float*)d_out;
    const long long BD = (long long)B * D;
    const long long BZ = (long long)B * Z;
    float* o_xe = out;
    float* o_xq = out + BD;
    float* o_ze = out + 2 * BD;
    float* o_zq = out + 2 * BD + BZ;
    float* o_k  = out + 2 * BD + 2 * BZ;
    float* o_zd = o_k + B;
    float* o_dp = o_zd + (long long)B * K;
    (void)out_size; (void)n_in;

    float* p_part;
    __nv_bfloat16 *p_w1h, *p_w1l, *p_w2eh, *p_w2el, *p_hdh, *p_hdl;
    cudaGetSymbolAddress((void**)&p_part, g_part);
    cudaGetSymbolAddress((void**)&p_w1h, g_w1h);
    cudaGetSymbolAddress((void**)&p_w1l, g_w1l);
    cudaGetSymbolAddress((void**)&p_w2eh, g_w2eh);
    cudaGetSymbolAddress((void**)&p_w2el, g_w2el);
    cudaGetSymbolAddress((void**)&p_hdh, g_hdh);
    cudaGetSymbolAddress((void**)&p_hdl, g_hdl);

    cudaFuncSetAttribute(mma_gemm_kernel<true>,
                         cudaFuncAttributeMaxDynamicSharedMemorySize, SMEM_TOTAL);
    cudaFuncSetAttribute(mma_gemm_kernel<false>,
                         cudaFuncAttributeMaxDynamicSharedMemorySize, SMEM_TOTAL);

    // --- weight prep ---
    {
        dim3 blk(32, 8);
        dim3 g1((KP1 + 31) / 32, (H + 31) / 32);
        transpose_split_kernel<<<g1, blk>>>(enc_w1, p_w1h, p_w1l, D, H, KP1, H);
        dim3 g2((H + 31) / 32, (NP2 + 31) / 32);
        transpose_split_kernel<<<g2, blk>>>(de_w2, p_w2eh, p_w2el, H, D, H, NP2);
    }

    // --- q-decoder table (only K=16 distinct rows), split-K parallel ---
    hq_kernel<<<1, 128>>>(emb, dq_w1, dq_b1, K, Z, H);
    {
        dim3 grid((D + 255) / 256, XQ_KSPLIT);
        xqtab_part_kernel<<<grid, 256>>>(dq_w2, K, H, D);
        xqtab_reduce_kernel<<<(K * D + 255) / 256, 256>>>(dq_b2, K, D);
    }

    // --- encoder GEMM1: fused fp32->split, uneven split-K=9 ---
    // (overwrites g_part, which xqtab_reduce has already consumed)
    {
        dim3 grid(1, B / 128, NSPLIT);
        mma_gemm_kernel<true><<<grid, 256, SMEM_TOTAL>>>(
            x, nullptr, nullptr, p_w1h, p_w1l, nullptr, p_part,
            /*lda=*/D, /*ldb=*/KP1, /*ldc=*/H, /*Nvalid=*/H, /*Dvalid=*/D,
            iPS, totalIters, /*splitStride=*/(long long)B * H);
    }
    h1_epilogue_kernel<<<(B * H + 255) / 256, 256>>>(enc_b1, B * H, H, NSPLIT);

    // --- z_e, clustering, e-decoder hidden ---
    zenc_kernel<<<B / (256 / Z), 256>>>(enc_w2, enc_b2, o_ze, B, H, Z);
    cluster_kernel<<<(B + 31) / 32, 32>>>(o_ze, emb, o_zq, o_k, o_zd, o_dp, B, Z, K);
    dec_h_e_kernel<<<B / 16, 128>>>(o_ze, de_w1, de_b1, B, Z, H);

    // --- x_q: gather from table ---
    {
        const int n = B * (D / 4);
        gather_xq_kernel<<<(n + 255) / 256, 256>>>(o_k, o_xq, B, D);
    }

    // --- e-decoder output GEMM ---
    {
        dim3 grid(NT2, B / 128, 1);
        mma_gemm_kernel<false><<<grid, 256, SMEM_TOTAL>>>(
            nullptr, p_hdh, p_hdl, p_w2eh, p_w2el, de_b2, o_xe,
            /*lda=*/H, /*ldb=*/H, /*ldc=*/D, /*Nvalid=*/D, /*Dvalid=*/D,
            /*itersPerSplit=*/H / 32, /*totalIters=*/H / 32, /*splitStride=*/0);
    }
}